// round 4
// baseline (speedup 1.0000x reference)
#include <cuda_runtime.h>
#include <math.h>
#include <stdint.h>

// Problem constants
#define BB 2
#define SS 2048
#define EE 2048
#define HH 16
#define DD 128
#define MM (BB*SS)   // 4096 rows for projection GEMMs

// Scratch (static __device__ — no allocation allowed)
__device__ float g_Q[(size_t)BB*HH*SS*DD];   // (B,H,S,D)
__device__ float g_K[(size_t)BB*HH*SS*DD];
__device__ float g_V[(size_t)BB*HH*SS*DD];
__device__ float g_AO[(size_t)BB*SS*EE];     // attention output (B,S,E)

// ---------------------------------------------------------------------------
// GEMM: Y = X[M,K] * W[K,N] + bias[N]
// MODE 0: Y row-major [M,N]
// MODE 1: Y in (B,H,S,D) layout: y[((b*H+h)*S+s)*D+d], h = blockIdx.x (N tile
//         width 128 == D so each N-tile is exactly one head)
// Block tile 128x128, BK=16, 256 threads, 8x8 per thread.
// ---------------------------------------------------------------------------
template<int MODE>
__global__ __launch_bounds__(256, 2)
void gemm_bias_kernel(const float* __restrict__ X, const float* __restrict__ W,
                      const float* __restrict__ bias, float* __restrict__ Y)
{
    const int K = EE, N = EE;
    __shared__ float Xs[16][128];  // [k][m]  (transposed)
    __shared__ float Ws[16][128];  // [k][n]

    const int tid = threadIdx.x;
    const int tx = tid & 15, ty = tid >> 4;
    const int bx = blockIdx.x, by = blockIdx.y;
    const int m0 = by * 128, n0 = bx * 128;

    float acc[8][8];
    #pragma unroll
    for (int i = 0; i < 8; i++)
        #pragma unroll
        for (int j = 0; j < 8; j++) acc[i][j] = 0.f;

    const float* Xp = X + (size_t)m0 * K;
    const float* Wp = W + n0;

    const int lr  = tid >> 2;   // 0..63  X row
    const int lk4 = tid & 3;    // 0..3   X k-float4
    const int wr  = tid >> 5;   // 0..7   W row
    const int wc4 = tid & 31;   // 0..31  W col-float4

    for (int k0 = 0; k0 < K; k0 += 16) {
        // X tile 128x16 -> Xs[k][m] (transposed)
        #pragma unroll
        for (int i = 0; i < 2; i++) {
            int r = lr + i * 64;
            float4 v = *(const float4*)(Xp + (size_t)r * K + k0 + lk4 * 4);
            Xs[lk4 * 4 + 0][r] = v.x;
            Xs[lk4 * 4 + 1][r] = v.y;
            Xs[lk4 * 4 + 2][r] = v.z;
            Xs[lk4 * 4 + 3][r] = v.w;
        }
        // W tile 16x128 -> Ws[k][n]
        #pragma unroll
        for (int i = 0; i < 2; i++) {
            int r = wr + i * 8;
            float4 v = *(const float4*)(Wp + (size_t)(k0 + r) * N + wc4 * 4);
            *(float4*)&Ws[r][wc4 * 4] = v;
        }
        __syncthreads();

        #pragma unroll
        for (int k = 0; k < 16; k++) {
            float a[8], b[8];
            *(float4*)&a[0] = *(float4*)&Xs[k][ty * 8];
            *(float4*)&a[4] = *(float4*)&Xs[k][ty * 8 + 4];
            *(float4*)&b[0] = *(float4*)&Ws[k][tx * 8];
            *(float4*)&b[4] = *(float4*)&Ws[k][tx * 8 + 4];
            #pragma unroll
            for (int i = 0; i < 8; i++)
                #pragma unroll
                for (int j = 0; j < 8; j++)
                    acc[i][j] += a[i] * b[j];
        }
        __syncthreads();
    }

    // epilogue
    float bj[8];
    #pragma unroll
    for (int j = 0; j < 8; j++) bj[j] = bias[n0 + tx * 8 + j];

    #pragma unroll
    for (int i = 0; i < 8; i++) {
        int row = m0 + ty * 8 + i;
        float4 v0, v1;
        v0.x = acc[i][0] + bj[0]; v0.y = acc[i][1] + bj[1];
        v0.z = acc[i][2] + bj[2]; v0.w = acc[i][3] + bj[3];
        v1.x = acc[i][4] + bj[4]; v1.y = acc[i][5] + bj[5];
        v1.z = acc[i][6] + bj[6]; v1.w = acc[i][7] + bj[7];
        if (MODE == 0) {
            float* yp = Y + (size_t)row * N + n0 + tx * 8;
            *(float4*)yp = v0;
            *(float4*)(yp + 4) = v1;
        } else {
            // (B,H,S,D): h = bx, d = tx*8+j
            int b = row >> 11;          // row / S
            int s = row & (SS - 1);     // row % S
            float* base = Y + ((size_t)(b * HH + bx) * SS + s) * DD + tx * 8;
            *(float4*)base = v0;
            *(float4*)(base + 4) = v1;
        }
    }
}

// ---------------------------------------------------------------------------
// Flash attention (fp32): per (b,h), 64-row Q tiles, stream 64-row KV tiles.
// Thread map (tx,ty) 16x16. Score tile element (r,c): r = ty+16i, c = tx+16j.
// O tile element (r,oc): r = ty+16i, oc = tx+16m  (m<8).
// Online softmax per row via 16-lane shuffles.
// ---------------------------------------------------------------------------
#define QS_STR 132   // 128 + 4 pad
#define PT_STR 68    // 64 + 4 pad

#define ATTN_SMEM_FLOATS (64*QS_STR /*Qs*/ + 64*QS_STR /*Ks*/ + 128*PT_STR /*Vt*/ + 64*PT_STR /*Ps*/)

__global__ __launch_bounds__(256, 1)
void attn_kernel(const float* __restrict__ Q, const float* __restrict__ K,
                 const float* __restrict__ V, float* __restrict__ AO)
{
    extern __shared__ float sm[];
    float* Qs = sm;                      // [64][QS_STR]
    float* Ks = Qs + 64 * QS_STR;        // [64][QS_STR]
    float* Vt = Ks + 64 * QS_STR;        // [128][PT_STR]  (V transposed: [d][c])
    float* Ps = Vt + 128 * PT_STR;       // [64][PT_STR]

    const int bh = blockIdx.y;           // 0..B*H-1
    const int q0 = blockIdx.x * 64;
    const int tid = threadIdx.x;
    const int tx = tid & 15, ty = tid >> 4;

    const float* Qg = Q + ((size_t)bh * SS + q0) * DD;
    const float* Kg = K + (size_t)bh * SS * DD;
    const float* Vg = V + (size_t)bh * SS * DD;

    // Load Q tile (64x128), natural layout
    for (int f = tid; f < 64 * 32; f += 256) {
        int r = f >> 5, d4 = f & 31;
        *(float4*)&Qs[r * QS_STR + d4 * 4] = *(const float4*)(Qg + (size_t)r * DD + d4 * 4);
    }

    float acc[4][8];
    #pragma unroll
    for (int i = 0; i < 4; i++)
        #pragma unroll
        for (int m = 0; m < 8; m++) acc[i][m] = 0.f;
    float mrow[4], lrow[4];
    #pragma unroll
    for (int i = 0; i < 4; i++) { mrow[i] = -1e30f; lrow[i] = 0.f; }

    const float scale = 0.08838834764831845f;  // 1/sqrt(128)

    for (int kt = 0; kt < SS; kt += 64) {
        __syncthreads();  // previous iteration done reading Ks/Vt/Ps
        // Load K tile (natural) and V tile (transposed)
        for (int f = tid; f < 64 * 32; f += 256) {
            int r = f >> 5, d4 = f & 31;
            *(float4*)&Ks[r * QS_STR + d4 * 4] =
                *(const float4*)(Kg + (size_t)(kt + r) * DD + d4 * 4);
            float4 v = *(const float4*)(Vg + (size_t)(kt + r) * DD + d4 * 4);
            Vt[(d4 * 4 + 0) * PT_STR + r] = v.x;
            Vt[(d4 * 4 + 1) * PT_STR + r] = v.y;
            Vt[(d4 * 4 + 2) * PT_STR + r] = v.z;
            Vt[(d4 * 4 + 3) * PT_STR + r] = v.w;
        }
        __syncthreads();

        // S tile = Q K^T
        float s[4][4];
        #pragma unroll
        for (int i = 0; i < 4; i++)
            #pragma unroll
            for (int j = 0; j < 4; j++) s[i][j] = 0.f;

        for (int d4 = 0; d4 < 32; d4++) {
            float4 q[4], kk[4];
            #pragma unroll
            for (int i = 0; i < 4; i++)
                q[i] = *(float4*)&Qs[(ty + 16 * i) * QS_STR + d4 * 4];
            #pragma unroll
            for (int j = 0; j < 4; j++)
                kk[j] = *(float4*)&Ks[(tx + 16 * j) * QS_STR + d4 * 4];
            #pragma unroll
            for (int i = 0; i < 4; i++)
                #pragma unroll
                for (int j = 0; j < 4; j++) {
                    s[i][j] += q[i].x * kk[j].x;
                    s[i][j] += q[i].y * kk[j].y;
                    s[i][j] += q[i].z * kk[j].z;
                    s[i][j] += q[i].w * kk[j].w;
                }
        }

        // Online softmax (per row r = ty+16i; row owned by 16 lanes w/ same ty)
        #pragma unroll
        for (int i = 0; i < 4; i++) {
            float mloc = -1e30f;
            #pragma unroll
            for (int j = 0; j < 4; j++) {
                s[i][j] *= scale;
                mloc = fmaxf(mloc, s[i][j]);
            }
            #pragma unroll
            for (int off = 1; off < 16; off <<= 1)
                mloc = fmaxf(mloc, __shfl_xor_sync(0xffffffffu, mloc, off));
            float mnew = fmaxf(mrow[i], mloc);
            float corr = __expf(mrow[i] - mnew);
            mrow[i] = mnew;
            float rsum = 0.f;
            float p[4];
            #pragma unroll
            for (int j = 0; j < 4; j++) {
                p[j] = __expf(s[i][j] - mnew);
                rsum += p[j];
            }
            #pragma unroll
            for (int off = 1; off < 16; off <<= 1)
                rsum += __shfl_xor_sync(0xffffffffu, rsum, off);
            lrow[i] = lrow[i] * corr + rsum;
            #pragma unroll
            for (int m = 0; m < 8; m++) acc[i][m] *= corr;
            #pragma unroll
            for (int j = 0; j < 4; j++)
                Ps[(ty + 16 * i) * PT_STR + tx + 16 * j] = p[j];
        }
        __syncthreads();

        // O += P @ V   (P[64x64] from Ps, V^T in Vt)
        for (int c4 = 0; c4 < 16; c4++) {
            float4 pv[4], vv[8];
            #pragma unroll
            for (int i = 0; i < 4; i++)
                pv[i] = *(float4*)&Ps[(ty + 16 * i) * PT_STR + c4 * 4];
            #pragma unroll
            for (int m = 0; m < 8; m++)
                vv[m] = *(float4*)&Vt[(tx + 16 * m) * PT_STR + c4 * 4];
            #pragma unroll
            for (int i = 0; i < 4; i++)
                #pragma unroll
                for (int m = 0; m < 8; m++) {
                    acc[i][m] += pv[i].x * vv[m].x;
                    acc[i][m] += pv[i].y * vv[m].y;
                    acc[i][m] += pv[i].z * vv[m].z;
                    acc[i][m] += pv[i].w * vv[m].w;
                }
        }
    }

    // Write (B,S,E)
    const int b = bh / HH, h = bh % HH;
    #pragma unroll
    for (int i = 0; i < 4; i++) {
        float inv = 1.0f / lrow[i];
        int srow = q0 + ty + 16 * i;
        float* op = AO + ((size_t)(b * SS + srow)) * EE + h * DD;
        #pragma unroll
        for (int m = 0; m < 8; m++)
            op[tx + 16 * m] = acc[i][m] * inv;
    }
}

// ---------------------------------------------------------------------------
extern "C" void kernel_launch(void* const* d_in, const int* in_sizes, int n_in,
                              void* d_out, int out_size)
{
    const float* query  = (const float*)d_in[0];
    const float* key_in = (const float*)d_in[1];
    const float* value  = (const float*)d_in[2];
    const float* Wq = (const float*)d_in[3];
    const float* bq = (const float*)d_in[4];
    const float* Wk = (const float*)d_in[5];
    const float* bk = (const float*)d_in[6];
    const float* Wv = (const float*)d_in[7];
    const float* bv = (const float*)d_in[8];
    const float* Wo = (const float*)d_in[9];
    const float* bo = (const float*)d_in[10];
    float* out = (float*)d_out;

    float *qbuf, *kbuf, *vbuf, *aobuf;
    cudaGetSymbolAddress((void**)&qbuf,  g_Q);
    cudaGetSymbolAddress((void**)&kbuf,  g_K);
    cudaGetSymbolAddress((void**)&vbuf,  g_V);
    cudaGetSymbolAddress((void**)&aobuf, g_AO);

    const size_t attn_smem = (size_t)ATTN_SMEM_FLOATS * sizeof(float);
    cudaFuncSetAttribute(attn_kernel,
                         cudaFuncAttributeMaxDynamicSharedMemorySize,
                         (int)attn_smem);

    dim3 gblock(256);
    dim3 ggrid(EE / 128, MM / 128);  // (16, 32)

    // Q/K/V projections -> (B,H,S,D)
    gemm_bias_kernel<1><<<ggrid, gblock>>>(query,  Wq, bq, qbuf);
    gemm_bias_kernel<1><<<ggrid, gblock>>>(key_in, Wk, bk, kbuf);
    gemm_bias_kernel<1><<<ggrid, gblock>>>(value,  Wv, bv, vbuf);

    // Fused attention -> (B,S,E)
    dim3 agrid(SS / 64, BB * HH);    // (32, 32)
    attn_kernel<<<agrid, dim3(256), attn_smem>>>(qbuf, kbuf, vbuf, aobuf);

    // Output projection -> d_out
    gemm_bias_kernel<0><<<ggrid, gblock>>>(aobuf, Wo, bo, out);
}

// round 5
// speedup vs baseline: 1.6905x; 1.6905x over previous
#include <cuda_runtime.h>
#include <math.h>
#include <stdint.h>

// Problem constants
#define BB 2
#define SS 2048
#define EE 2048
#define HH 16
#define DD 128
#define MM (BB*SS)   // 4096 rows for projection GEMMs

// Scratch (static __device__ — no allocation allowed)
__device__ float g_Q[(size_t)BB*HH*SS*DD];   // (B,H,S,D)
__device__ float g_K[(size_t)BB*HH*SS*DD];
__device__ float g_V[(size_t)BB*HH*SS*DD];
__device__ float g_AO[(size_t)BB*SS*EE];     // attention output (B,S,E), tf32-rounded

// tf32-converted copies of inputs
__device__ float g_cq[(size_t)MM*EE];
__device__ float g_ck[(size_t)MM*EE];
__device__ float g_cv[(size_t)MM*EE];
__device__ float g_cWq[(size_t)EE*EE];
__device__ float g_cWk[(size_t)EE*EE];
__device__ float g_cWv[(size_t)EE*EE];
__device__ float g_cWo[(size_t)EE*EE];

// ---------------------------------------------------------------------------
// Elementwise fp32 -> tf32(RN) conversion (bits kept in fp32 container)
// ---------------------------------------------------------------------------
__device__ __forceinline__ float to_tf32(float x) {
    uint32_t u;
    asm("cvt.rna.tf32.f32 %0, %1;" : "=r"(u) : "f"(x));
    return __uint_as_float(u);
}

__global__ void cvt_tf32_kernel(const float* __restrict__ in, float* __restrict__ out, int n4)
{
    int i = blockIdx.x * blockDim.x + threadIdx.x;
    if (i < n4) {
        float4 v = ((const float4*)in)[i];
        v.x = to_tf32(v.x); v.y = to_tf32(v.y);
        v.z = to_tf32(v.z); v.w = to_tf32(v.w);
        ((float4*)out)[i] = v;
    }
}

// ---------------------------------------------------------------------------
// tf32 tensor-core GEMM: Y = X[M,K] * W[K,N] + bias
// MODE 0: Y row-major [M,N];  MODE 1: Y in (B,H,S,D), head = blockIdx.x
// Block 128x128, BK=32, 256 thr (8 warps, 2x4), warp tile 64x32, mma m16n8k8.
// cp.async double-buffered. Inputs must already be tf32-rounded bits.
// ---------------------------------------------------------------------------
#define BK 32
#define ASTR 36    // 32+4: a-frag bank = (4g+t)%32, bijective
#define BSTR 136   // 128+8: b-frag bank = (8t+g)%32, bijective
#define GEMM_SMEM ((2*128*ASTR + 2*BK*BSTR) * 4)

#define CP_ASYNC16(sa, gp) asm volatile("cp.async.cg.shared.global [%0], [%1], 16;\n" :: "r"(sa), "l"(gp))
#define CP_COMMIT()        asm volatile("cp.async.commit_group;\n")
#define CP_WAIT1()         asm volatile("cp.async.wait_group 1;\n")
#define CP_WAIT0()         asm volatile("cp.async.wait_group 0;\n")

__device__ __forceinline__ void mma_tf32(float c[4], const uint32_t a[4], const uint32_t b[2])
{
    asm volatile(
        "mma.sync.aligned.m16n8k8.row.col.f32.tf32.tf32.f32 "
        "{%0,%1,%2,%3}, {%4,%5,%6,%7}, {%8,%9}, {%0,%1,%2,%3};\n"
        : "+f"(c[0]), "+f"(c[1]), "+f"(c[2]), "+f"(c[3])
        : "r"(a[0]), "r"(a[1]), "r"(a[2]), "r"(a[3]), "r"(b[0]), "r"(b[1]));
}

template<int MODE>
__global__ __launch_bounds__(256, 2)
void gemm_tf32_kernel(const float* __restrict__ X, const float* __restrict__ W,
                      const float* __restrict__ bias, float* __restrict__ Y)
{
    extern __shared__ float sm[];
    float* Abuf = sm;                    // 2 stages of [128][ASTR]
    float* Bbuf = sm + 2 * 128 * ASTR;   // 2 stages of [BK][BSTR]

    const int tid  = threadIdx.x;
    const int lane = tid & 31;
    const int warp = tid >> 5;
    const int g = lane >> 2, t = lane & 3;
    const int wm = (warp >> 2) * 64;   // warp M offset (0 or 64)
    const int wn = (warp & 3) * 32;    // warp N offset (0,32,64,96)
    const int m0 = blockIdx.y * 128, n0 = blockIdx.x * 128;

    const int NT = EE / BK;  // 64 k-tiles

    float acc[4][4][4];
    #pragma unroll
    for (int mi = 0; mi < 4; mi++)
        #pragma unroll
        for (int ni = 0; ni < 4; ni++)
            #pragma unroll
            for (int r = 0; r < 4; r++) acc[mi][ni][r] = 0.f;

    // cp.async chunk mapping (per thread: 4 A-chunks + 4 B-chunks of 16B)
    auto issue_tile = [&](int stage, int k0) {
        float* As = Abuf + stage * 128 * ASTR;
        float* Bs = Bbuf + stage * BK * BSTR;
        #pragma unroll
        for (int j = 0; j < 4; j++) {
            int c = tid + j * 256;
            int m = c >> 3, kc = c & 7;
            uint32_t sa = (uint32_t)__cvta_generic_to_shared(As + m * ASTR + kc * 4);
            const float* gp = X + (size_t)(m0 + m) * EE + k0 + kc * 4;
            CP_ASYNC16(sa, gp);
        }
        #pragma unroll
        for (int j = 0; j < 4; j++) {
            int c = tid + j * 256;
            int k = c >> 5, nc = c & 31;
            uint32_t sb = (uint32_t)__cvta_generic_to_shared(Bs + k * BSTR + nc * 4);
            const float* gp = W + (size_t)(k0 + k) * EE + n0 + nc * 4;
            CP_ASYNC16(sb, gp);
        }
    };

    issue_tile(0, 0);
    CP_COMMIT();

    for (int it = 0; it < NT; it++) {
        if (it + 1 < NT) {
            issue_tile((it + 1) & 1, (it + 1) * BK);
            CP_COMMIT();
            CP_WAIT1();
        } else {
            CP_WAIT0();
        }
        __syncthreads();

        const float* As = Abuf + (it & 1) * 128 * ASTR;
        const float* Bs = Bbuf + (it & 1) * BK * BSTR;

        #pragma unroll
        for (int ks = 0; ks < 4; ks++) {
            const int kk = ks * 8;
            uint32_t a[4][4], b[4][2];
            #pragma unroll
            for (int mi = 0; mi < 4; mi++) {
                const float* ap = As + (wm + mi * 16 + g) * ASTR + kk + t;
                a[mi][0] = __float_as_uint(ap[0]);
                a[mi][1] = __float_as_uint(ap[8 * ASTR]);
                a[mi][2] = __float_as_uint(ap[4]);
                a[mi][3] = __float_as_uint(ap[8 * ASTR + 4]);
            }
            #pragma unroll
            for (int ni = 0; ni < 4; ni++) {
                const float* bp = Bs + (kk + t) * BSTR + wn + ni * 8 + g;
                b[ni][0] = __float_as_uint(bp[0]);
                b[ni][1] = __float_as_uint(bp[4 * BSTR]);
            }
            #pragma unroll
            for (int mi = 0; mi < 4; mi++)
                #pragma unroll
                for (int ni = 0; ni < 4; ni++)
                    mma_tf32(acc[mi][ni], a[mi], b[ni]);
        }
        __syncthreads();
    }

    // Epilogue: c0=(g,2t) c1=(g,2t+1) c2=(g+8,2t) c3=(g+8,2t+1) per 16x8 tile
    #pragma unroll
    for (int mi = 0; mi < 4; mi++) {
        #pragma unroll
        for (int ni = 0; ni < 4; ni++) {
            int row = m0 + wm + mi * 16 + g;
            int cl  = wn + ni * 8 + 2 * t;      // column within 128-wide tile
            int n   = n0 + cl;
            float2 v0, v1;
            v0.x = acc[mi][ni][0] + bias[n];
            v0.y = acc[mi][ni][1] + bias[n + 1];
            v1.x = acc[mi][ni][2] + bias[n];
            v1.y = acc[mi][ni][3] + bias[n + 1];
            if (MODE == 0) {
                *(float2*)(Y + (size_t)row * EE + n) = v0;
                *(float2*)(Y + (size_t)(row + 8) * EE + n) = v1;
            } else {
                int b0r = row >> 11, s = row & (SS - 1);
                float* base = Y + ((size_t)(b0r * HH + blockIdx.x) * SS + s) * DD + cl;
                *(float2*)base = v0;
                int s2 = (row + 8) & (SS - 1);
                float* base2 = Y + ((size_t)(b0r * HH + blockIdx.x) * SS + s2) * DD + cl;
                *(float2*)base2 = v1;
            }
        }
    }
}

// ---------------------------------------------------------------------------
// Flash attention (fp32) — unchanged except tf32 rounding at output store
// ---------------------------------------------------------------------------
#define QS_STR 132
#define PT_STR 68
#define ATTN_SMEM_FLOATS (64*QS_STR + 64*QS_STR + 128*PT_STR + 64*PT_STR)

__global__ __launch_bounds__(256, 1)
void attn_kernel(const float* __restrict__ Q, const float* __restrict__ K,
                 const float* __restrict__ V, float* __restrict__ AO)
{
    extern __shared__ float sm[];
    float* Qs = sm;
    float* Ks = Qs + 64 * QS_STR;
    float* Vt = Ks + 64 * QS_STR;
    float* Ps = Vt + 128 * PT_STR;

    const int bh = blockIdx.y;
    const int q0 = blockIdx.x * 64;
    const int tid = threadIdx.x;
    const int tx = tid & 15, ty = tid >> 4;

    const float* Qg = Q + ((size_t)bh * SS + q0) * DD;
    const float* Kg = K + (size_t)bh * SS * DD;
    const float* Vg = V + (size_t)bh * SS * DD;

    for (int f = tid; f < 64 * 32; f += 256) {
        int r = f >> 5, d4 = f & 31;
        *(float4*)&Qs[r * QS_STR + d4 * 4] = *(const float4*)(Qg + (size_t)r * DD + d4 * 4);
    }

    float acc[4][8];
    #pragma unroll
    for (int i = 0; i < 4; i++)
        #pragma unroll
        for (int m = 0; m < 8; m++) acc[i][m] = 0.f;
    float mrow[4], lrow[4];
    #pragma unroll
    for (int i = 0; i < 4; i++) { mrow[i] = -1e30f; lrow[i] = 0.f; }

    const float scale = 0.08838834764831845f;

    for (int kt = 0; kt < SS; kt += 64) {
        __syncthreads();
        for (int f = tid; f < 64 * 32; f += 256) {
            int r = f >> 5, d4 = f & 31;
            *(float4*)&Ks[r * QS_STR + d4 * 4] =
                *(const float4*)(Kg + (size_t)(kt + r) * DD + d4 * 4);
            float4 v = *(const float4*)(Vg + (size_t)(kt + r) * DD + d4 * 4);
            Vt[(d4 * 4 + 0) * PT_STR + r] = v.x;
            Vt[(d4 * 4 + 1) * PT_STR + r] = v.y;
            Vt[(d4 * 4 + 2) * PT_STR + r] = v.z;
            Vt[(d4 * 4 + 3) * PT_STR + r] = v.w;
        }
        __syncthreads();

        float s[4][4];
        #pragma unroll
        for (int i = 0; i < 4; i++)
            #pragma unroll
            for (int j = 0; j < 4; j++) s[i][j] = 0.f;

        for (int d4 = 0; d4 < 32; d4++) {
            float4 q[4], kk[4];
            #pragma unroll
            for (int i = 0; i < 4; i++)
                q[i] = *(float4*)&Qs[(ty + 16 * i) * QS_STR + d4 * 4];
            #pragma unroll
            for (int j = 0; j < 4; j++)
                kk[j] = *(float4*)&Ks[(tx + 16 * j) * QS_STR + d4 * 4];
            #pragma unroll
            for (int i = 0; i < 4; i++)
                #pragma unroll
                for (int j = 0; j < 4; j++) {
                    s[i][j] += q[i].x * kk[j].x;
                    s[i][j] += q[i].y * kk[j].y;
                    s[i][j] += q[i].z * kk[j].z;
                    s[i][j] += q[i].w * kk[j].w;
                }
        }

        #pragma unroll
        for (int i = 0; i < 4; i++) {
            float mloc = -1e30f;
            #pragma unroll
            for (int j = 0; j < 4; j++) {
                s[i][j] *= scale;
                mloc = fmaxf(mloc, s[i][j]);
            }
            #pragma unroll
            for (int off = 1; off < 16; off <<= 1)
                mloc = fmaxf(mloc, __shfl_xor_sync(0xffffffffu, mloc, off));
            float mnew = fmaxf(mrow[i], mloc);
            float corr = __expf(mrow[i] - mnew);
            mrow[i] = mnew;
            float rsum = 0.f;
            float p[4];
            #pragma unroll
            for (int j = 0; j < 4; j++) {
                p[j] = __expf(s[i][j] - mnew);
                rsum += p[j];
            }
            #pragma unroll
            for (int off = 1; off < 16; off <<= 1)
                rsum += __shfl_xor_sync(0xffffffffu, rsum, off);
            lrow[i] = lrow[i] * corr + rsum;
            #pragma unroll
            for (int m = 0; m < 8; m++) acc[i][m] *= corr;
            #pragma unroll
            for (int j = 0; j < 4; j++)
                Ps[(ty + 16 * i) * PT_STR + tx + 16 * j] = p[j];
        }
        __syncthreads();

        for (int c4 = 0; c4 < 16; c4++) {
            float4 pv[4], vv[8];
            #pragma unroll
            for (int i = 0; i < 4; i++)
                pv[i] = *(float4*)&Ps[(ty + 16 * i) * PT_STR + c4 * 4];
            #pragma unroll
            for (int m = 0; m < 8; m++)
                vv[m] = *(float4*)&Vt[(tx + 16 * m) * PT_STR + c4 * 4];
            #pragma unroll
            for (int i = 0; i < 4; i++)
                #pragma unroll
                for (int m = 0; m < 8; m++) {
                    acc[i][m] += pv[i].x * vv[m].x;
                    acc[i][m] += pv[i].y * vv[m].y;
                    acc[i][m] += pv[i].z * vv[m].z;
                    acc[i][m] += pv[i].w * vv[m].w;
                }
        }
    }

    const int b = bh / HH, h = bh % HH;
    #pragma unroll
    for (int i = 0; i < 4; i++) {
        float inv = 1.0f / lrow[i];
        int srow = q0 + ty + 16 * i;
        float* op = AO + ((size_t)(b * SS + srow)) * EE + h * DD;
        #pragma unroll
        for (int m = 0; m < 8; m++)
            op[tx + 16 * m] = to_tf32(acc[i][m] * inv);  // tf32-round for Wo GEMM
    }
}

// ---------------------------------------------------------------------------
extern "C" void kernel_launch(void* const* d_in, const int* in_sizes, int n_in,
                              void* d_out, int out_size)
{
    const float* query  = (const float*)d_in[0];
    const float* key_in = (const float*)d_in[1];
    const float* value  = (const float*)d_in[2];
    const float* Wq = (const float*)d_in[3];
    const float* bq = (const float*)d_in[4];
    const float* Wk = (const float*)d_in[5];
    const float* bk = (const float*)d_in[6];
    const float* Wv = (const float*)d_in[7];
    const float* bv = (const float*)d_in[8];
    const float* Wo = (const float*)d_in[9];
    const float* bo = (const float*)d_in[10];
    float* out = (float*)d_out;

    float *qbuf, *kbuf, *vbuf, *aobuf;
    float *cq, *ck, *cv, *cWq, *cWk, *cWv, *cWo;
    cudaGetSymbolAddress((void**)&qbuf,  g_Q);
    cudaGetSymbolAddress((void**)&kbuf,  g_K);
    cudaGetSymbolAddress((void**)&vbuf,  g_V);
    cudaGetSymbolAddress((void**)&aobuf, g_AO);
    cudaGetSymbolAddress((void**)&cq,  g_cq);
    cudaGetSymbolAddress((void**)&ck,  g_ck);
    cudaGetSymbolAddress((void**)&cv,  g_cv);
    cudaGetSymbolAddress((void**)&cWq, g_cWq);
    cudaGetSymbolAddress((void**)&cWk, g_cWk);
    cudaGetSymbolAddress((void**)&cWv, g_cWv);
    cudaGetSymbolAddress((void**)&cWo, g_cWo);

    const size_t attn_smem = (size_t)ATTN_SMEM_FLOATS * sizeof(float);
    cudaFuncSetAttribute(attn_kernel,
                         cudaFuncAttributeMaxDynamicSharedMemorySize, (int)attn_smem);
    cudaFuncSetAttribute(gemm_tf32_kernel<0>,
                         cudaFuncAttributeMaxDynamicSharedMemorySize, GEMM_SMEM);
    cudaFuncSetAttribute(gemm_tf32_kernel<1>,
                         cudaFuncAttributeMaxDynamicSharedMemorySize, GEMM_SMEM);

    // 1. tf32 conversion of inputs
    const int NX4 = MM * EE / 4, NW4 = EE * EE / 4;
    cvt_tf32_kernel<<<(NX4 + 255) / 256, 256>>>(query,  cq,  NX4);
    cvt_tf32_kernel<<<(NX4 + 255) / 256, 256>>>(key_in, ck,  NX4);
    cvt_tf32_kernel<<<(NX4 + 255) / 256, 256>>>(value,  cv,  NX4);
    cvt_tf32_kernel<<<(NW4 + 255) / 256, 256>>>(Wq, cWq, NW4);
    cvt_tf32_kernel<<<(NW4 + 255) / 256, 256>>>(Wk, cWk, NW4);
    cvt_tf32_kernel<<<(NW4 + 255) / 256, 256>>>(Wv, cWv, NW4);
    cvt_tf32_kernel<<<(NW4 + 255) / 256, 256>>>(Wo, cWo, NW4);

    dim3 gblock(256);
    dim3 ggrid(EE / 128, MM / 128);  // (16, 32)

    // 2. Q/K/V projections (tf32 tensor cores) -> (B,H,S,D)
    gemm_tf32_kernel<1><<<ggrid, gblock, GEMM_SMEM>>>(cq, cWq, bq, qbuf);
    gemm_tf32_kernel<1><<<ggrid, gblock, GEMM_SMEM>>>(ck, cWk, bk, kbuf);
    gemm_tf32_kernel<1><<<ggrid, gblock, GEMM_SMEM>>>(cv, cWv, bv, vbuf);

    // 3. Fused attention (fp32) -> (B,S,E) tf32-rounded
    dim3 agrid(SS / 64, BB * HH);
    attn_kernel<<<agrid, dim3(256), attn_smem>>>(qbuf, kbuf, vbuf, aobuf);

    // 4. Output projection (tf32 tensor cores) -> d_out
    gemm_tf32_kernel<0><<<ggrid, gblock, GEMM_SMEM>>>(aobuf, cWo, bo, out);
}

// round 6
// speedup vs baseline: 3.8581x; 2.2822x over previous
#include <cuda_runtime.h>
#include <math.h>
#include <stdint.h>

// Problem constants
#define BB 2
#define SS 2048
#define EE 2048
#define HH 16
#define DD 128
#define MM (BB*SS)   // 4096 rows for projection GEMMs

// Scratch (static __device__ — no allocation allowed)
__device__ float g_Q[(size_t)BB*HH*SS*DD];   // (B,H,S,D), tf32-rounded
__device__ float g_K[(size_t)BB*HH*SS*DD];
__device__ float g_V[(size_t)BB*HH*SS*DD];
__device__ float g_AO[(size_t)BB*SS*EE];     // attention output (B,S,E), tf32-rounded

// tf32-converted copies of inputs
__device__ float g_cq[(size_t)MM*EE];
__device__ float g_ck[(size_t)MM*EE];
__device__ float g_cv[(size_t)MM*EE];
__device__ float g_cWq[(size_t)EE*EE];
__device__ float g_cWk[(size_t)EE*EE];
__device__ float g_cWv[(size_t)EE*EE];
__device__ float g_cWo[(size_t)EE*EE];

// ---------------------------------------------------------------------------
__device__ __forceinline__ float to_tf32(float x) {
    uint32_t u;
    asm("cvt.rna.tf32.f32 %0, %1;" : "=r"(u) : "f"(x));
    return __uint_as_float(u);
}

__global__ void cvt_tf32_kernel(const float* __restrict__ in, float* __restrict__ out, int n4)
{
    int i = blockIdx.x * blockDim.x + threadIdx.x;
    if (i < n4) {
        float4 v = ((const float4*)in)[i];
        v.x = to_tf32(v.x); v.y = to_tf32(v.y);
        v.z = to_tf32(v.z); v.w = to_tf32(v.w);
        ((float4*)out)[i] = v;
    }
}

// ---------------------------------------------------------------------------
// tf32 tensor-core GEMM (unchanged from R4 except MODE1 stores tf32-rounded)
// ---------------------------------------------------------------------------
#define BK 32
#define ASTR 36
#define BSTR 136
#define GEMM_SMEM ((2*128*ASTR + 2*BK*BSTR) * 4)

#define CP_ASYNC16(sa, gp) asm volatile("cp.async.cg.shared.global [%0], [%1], 16;\n" :: "r"(sa), "l"(gp))
#define CP_COMMIT()        asm volatile("cp.async.commit_group;\n")
#define CP_WAIT1()         asm volatile("cp.async.wait_group 1;\n")
#define CP_WAIT0()         asm volatile("cp.async.wait_group 0;\n")

__device__ __forceinline__ void mma_tf32(float c[4], const uint32_t a[4], const uint32_t b[2])
{
    asm volatile(
        "mma.sync.aligned.m16n8k8.row.col.f32.tf32.tf32.f32 "
        "{%0,%1,%2,%3}, {%4,%5,%6,%7}, {%8,%9}, {%0,%1,%2,%3};\n"
        : "+f"(c[0]), "+f"(c[1]), "+f"(c[2]), "+f"(c[3])
        : "r"(a[0]), "r"(a[1]), "r"(a[2]), "r"(a[3]), "r"(b[0]), "r"(b[1]));
}

template<int MODE>
__global__ __launch_bounds__(256, 2)
void gemm_tf32_kernel(const float* __restrict__ X, const float* __restrict__ W,
                      const float* __restrict__ bias, float* __restrict__ Y)
{
    extern __shared__ float sm[];
    float* Abuf = sm;
    float* Bbuf = sm + 2 * 128 * ASTR;

    const int tid  = threadIdx.x;
    const int lane = tid & 31;
    const int warp = tid >> 5;
    const int g = lane >> 2, t = lane & 3;
    const int wm = (warp >> 2) * 64;
    const int wn = (warp & 3) * 32;
    const int m0 = blockIdx.y * 128, n0 = blockIdx.x * 128;

    const int NT = EE / BK;

    float acc[4][4][4];
    #pragma unroll
    for (int mi = 0; mi < 4; mi++)
        #pragma unroll
        for (int ni = 0; ni < 4; ni++)
            #pragma unroll
            for (int r = 0; r < 4; r++) acc[mi][ni][r] = 0.f;

    auto issue_tile = [&](int stage, int k0) {
        float* As = Abuf + stage * 128 * ASTR;
        float* Bs = Bbuf + stage * BK * BSTR;
        #pragma unroll
        for (int j = 0; j < 4; j++) {
            int c = tid + j * 256;
            int m = c >> 3, kc = c & 7;
            uint32_t sa = (uint32_t)__cvta_generic_to_shared(As + m * ASTR + kc * 4);
            CP_ASYNC16(sa, X + (size_t)(m0 + m) * EE + k0 + kc * 4);
        }
        #pragma unroll
        for (int j = 0; j < 4; j++) {
            int c = tid + j * 256;
            int k = c >> 5, nc = c & 31;
            uint32_t sb = (uint32_t)__cvta_generic_to_shared(Bs + k * BSTR + nc * 4);
            CP_ASYNC16(sb, W + (size_t)(k0 + k) * EE + n0 + nc * 4);
        }
    };

    issue_tile(0, 0);
    CP_COMMIT();

    for (int it = 0; it < NT; it++) {
        if (it + 1 < NT) {
            issue_tile((it + 1) & 1, (it + 1) * BK);
            CP_COMMIT();
            CP_WAIT1();
        } else {
            CP_WAIT0();
        }
        __syncthreads();

        const float* As = Abuf + (it & 1) * 128 * ASTR;
        const float* Bs = Bbuf + (it & 1) * BK * BSTR;

        #pragma unroll
        for (int ks = 0; ks < 4; ks++) {
            const int kk = ks * 8;
            uint32_t a[4][4], b[4][2];
            #pragma unroll
            for (int mi = 0; mi < 4; mi++) {
                const float* ap = As + (wm + mi * 16 + g) * ASTR + kk + t;
                a[mi][0] = __float_as_uint(ap[0]);
                a[mi][1] = __float_as_uint(ap[8 * ASTR]);
                a[mi][2] = __float_as_uint(ap[4]);
                a[mi][3] = __float_as_uint(ap[8 * ASTR + 4]);
            }
            #pragma unroll
            for (int ni = 0; ni < 4; ni++) {
                const float* bp = Bs + (kk + t) * BSTR + wn + ni * 8 + g;
                b[ni][0] = __float_as_uint(bp[0]);
                b[ni][1] = __float_as_uint(bp[4 * BSTR]);
            }
            #pragma unroll
            for (int mi = 0; mi < 4; mi++)
                #pragma unroll
                for (int ni = 0; ni < 4; ni++)
                    mma_tf32(acc[mi][ni], a[mi], b[ni]);
        }
        __syncthreads();
    }

    #pragma unroll
    for (int mi = 0; mi < 4; mi++) {
        #pragma unroll
        for (int ni = 0; ni < 4; ni++) {
            int row = m0 + wm + mi * 16 + g;
            int cl  = wn + ni * 8 + 2 * t;
            int n   = n0 + cl;
            float2 v0, v1;
            v0.x = acc[mi][ni][0] + bias[n];
            v0.y = acc[mi][ni][1] + bias[n + 1];
            v1.x = acc[mi][ni][2] + bias[n];
            v1.y = acc[mi][ni][3] + bias[n + 1];
            if (MODE == 0) {
                *(float2*)(Y + (size_t)row * EE + n) = v0;
                *(float2*)(Y + (size_t)(row + 8) * EE + n) = v1;
            } else {
                // tf32-round Q/K/V at storage so attention mma reads exact bits
                v0.x = to_tf32(v0.x); v0.y = to_tf32(v0.y);
                v1.x = to_tf32(v1.x); v1.y = to_tf32(v1.y);
                int b0r = row >> 11, s = row & (SS - 1);
                float* base = Y + ((size_t)(b0r * HH + blockIdx.x) * SS + s) * DD + cl;
                *(float2*)base = v0;
                int s2 = (row + 8) & (SS - 1);
                float* base2 = Y + ((size_t)(b0r * HH + blockIdx.x) * SS + s2) * DD + cl;
                *(float2*)base2 = v1;
            }
        }
    }
}

// ---------------------------------------------------------------------------
// tf32 tensor-core flash attention
// CTA: 256 thr / 8 warps; Q tile 128 (warp w owns rows 16w..16w+15); KV tile 64.
// Q in register fragments; K/V double-buffered smem (cp.async); P via per-warp smem.
// Strides: K 132 (bank 4g+t), V 136 (bank 8t+g), P 68 (bank 4g+t) — conflict-free.
// ---------------------------------------------------------------------------
#define TK 64
#define KSTR 132
#define VSTR 136
#define PSTR 68
#define ATTN2_SMEM_FLOATS (2*TK*KSTR + 2*TK*VSTR + 8*16*PSTR)

__global__ __launch_bounds__(256, 1)
void attn_tc_kernel(const float* __restrict__ Q, const float* __restrict__ K,
                    const float* __restrict__ V, float* __restrict__ AO)
{
    extern __shared__ float sm[];
    float* Kb = sm;                       // [2][TK][KSTR]
    float* Vb = sm + 2 * TK * KSTR;       // [2][TK][VSTR]
    float* Pw = Vb + 2 * TK * VSTR;       // [8][16][PSTR]

    const int tid  = threadIdx.x;
    const int lane = tid & 31;
    const int warp = tid >> 5;
    const int g = lane >> 2, t = lane & 3;
    const int bh = blockIdx.y;
    const int q0 = blockIdx.x * 128;

    const float* Qg = Q + ((size_t)bh * SS + q0) * DD;
    const float* Kg = K + (size_t)bh * SS * DD;
    const float* Vg = V + (size_t)bh * SS * DD;

    // ---- stage Q (128x128) into Kb (both stages, 128x132), then to regs ----
    #pragma unroll
    for (int j = 0; j < 16; j++) {
        int c = tid + j * 256;            // 0..4095
        int r = c >> 5, c4 = c & 31;
        uint32_t sa = (uint32_t)__cvta_generic_to_shared(Kb + r * KSTR + c4 * 4);
        CP_ASYNC16(sa, Qg + (size_t)r * DD + c4 * 4);
    }
    CP_COMMIT(); CP_WAIT0();
    __syncthreads();

    uint32_t qa[16][4];
    {
        const float* qp = Kb + (warp * 16 + g) * KSTR + t;
        #pragma unroll
        for (int ks = 0; ks < 16; ks++) {
            qa[ks][0] = __float_as_uint(qp[8 * ks]);
            qa[ks][1] = __float_as_uint(qp[8 * KSTR + 8 * ks]);
            qa[ks][2] = __float_as_uint(qp[8 * ks + 4]);
            qa[ks][3] = __float_as_uint(qp[8 * KSTR + 8 * ks + 4]);
        }
    }
    __syncthreads();  // all warps done reading Q; Kb reusable

    float oacc[16][4];
    #pragma unroll
    for (int n = 0; n < 16; n++)
        #pragma unroll
        for (int r = 0; r < 4; r++) oacc[n][r] = 0.f;
    float m_a = -1e30f, m_b = -1e30f, l_a = 0.f, l_b = 0.f;

    const float scale = 0.08838834764831845f;  // 1/sqrt(128)

    auto load_kv = [&](int stage, int kt) {
        float* Ks_ = Kb + stage * TK * KSTR;
        float* Vs_ = Vb + stage * TK * VSTR;
        #pragma unroll
        for (int j = 0; j < 8; j++) {
            int c = tid + j * 256;        // 0..2047
            int r = c >> 5, c4 = c & 31;
            uint32_t sk = (uint32_t)__cvta_generic_to_shared(Ks_ + r * KSTR + c4 * 4);
            CP_ASYNC16(sk, Kg + (size_t)(kt + r) * DD + c4 * 4);
            uint32_t sv = (uint32_t)__cvta_generic_to_shared(Vs_ + r * VSTR + c4 * 4);
            CP_ASYNC16(sv, Vg + (size_t)(kt + r) * DD + c4 * 4);
        }
    };

    load_kv(0, 0);
    CP_COMMIT();

    const int NTILES = SS / TK;  // 32
    for (int it = 0; it < NTILES; it++) {
        if (it + 1 < NTILES) {
            load_kv((it + 1) & 1, (it + 1) * TK);
            CP_COMMIT();
            CP_WAIT1();
        } else {
            CP_WAIT0();
        }
        __syncthreads();

        const float* Ks_ = Kb + (it & 1) * TK * KSTR;
        const float* Vs_ = Vb + (it & 1) * TK * VSTR;

        // ---- S = Q K^T  (warp: 16 q-rows x 64 kv) ----
        float sacc[8][4];
        #pragma unroll
        for (int n = 0; n < 8; n++)
            #pragma unroll
            for (int r = 0; r < 4; r++) sacc[n][r] = 0.f;

        #pragma unroll
        for (int ks = 0; ks < 16; ks++) {
            #pragma unroll
            for (int nt = 0; nt < 8; nt++) {
                uint32_t b[2];
                const float* bp = Ks_ + (nt * 8 + g) * KSTR + 8 * ks + t;
                b[0] = __float_as_uint(bp[0]);
                b[1] = __float_as_uint(bp[4]);
                mma_tf32(sacc[nt], qa[ks], b);
            }
        }

        // ---- online softmax (rows g and g+8; 4 lanes/row share via xor 1,2) ----
        float mxa = -1e30f, mxb = -1e30f;
        #pragma unroll
        for (int nt = 0; nt < 8; nt++) {
            sacc[nt][0] *= scale; sacc[nt][1] *= scale;
            sacc[nt][2] *= scale; sacc[nt][3] *= scale;
            mxa = fmaxf(mxa, fmaxf(sacc[nt][0], sacc[nt][1]));
            mxb = fmaxf(mxb, fmaxf(sacc[nt][2], sacc[nt][3]));
        }
        mxa = fmaxf(mxa, __shfl_xor_sync(0xffffffffu, mxa, 1));
        mxa = fmaxf(mxa, __shfl_xor_sync(0xffffffffu, mxa, 2));
        mxb = fmaxf(mxb, __shfl_xor_sync(0xffffffffu, mxb, 1));
        mxb = fmaxf(mxb, __shfl_xor_sync(0xffffffffu, mxb, 2));

        float mna = fmaxf(m_a, mxa), mnb = fmaxf(m_b, mxb);
        float ca = __expf(m_a - mna), cb = __expf(m_b - mnb);
        m_a = mna; m_b = mnb;

        float ra = 0.f, rb = 0.f;
        float* pw = Pw + warp * 16 * PSTR;
        #pragma unroll
        for (int nt = 0; nt < 8; nt++) {
            float p0 = to_tf32(__expf(sacc[nt][0] - mna));
            float p1 = to_tf32(__expf(sacc[nt][1] - mna));
            float p2 = to_tf32(__expf(sacc[nt][2] - mnb));
            float p3 = to_tf32(__expf(sacc[nt][3] - mnb));
            ra += p0 + p1; rb += p2 + p3;
            *(float2*)&pw[g * PSTR + nt * 8 + 2 * t]       = make_float2(p0, p1);
            *(float2*)&pw[(g + 8) * PSTR + nt * 8 + 2 * t] = make_float2(p2, p3);
        }
        ra += __shfl_xor_sync(0xffffffffu, ra, 1);
        ra += __shfl_xor_sync(0xffffffffu, ra, 2);
        rb += __shfl_xor_sync(0xffffffffu, rb, 1);
        rb += __shfl_xor_sync(0xffffffffu, rb, 2);
        l_a = l_a * ca + ra;
        l_b = l_b * cb + rb;

        #pragma unroll
        for (int n = 0; n < 16; n++) {
            oacc[n][0] *= ca; oacc[n][1] *= ca;
            oacc[n][2] *= cb; oacc[n][3] *= cb;
        }
        __syncwarp();  // P visible within warp

        // ---- O += P V  (warp: 16 rows x 128 d) ----
        #pragma unroll
        for (int k2 = 0; k2 < 8; k2++) {
            uint32_t pa[4];
            const float* pp = pw + g * PSTR + 8 * k2 + t;
            pa[0] = __float_as_uint(pp[0]);
            pa[1] = __float_as_uint(pp[8 * PSTR]);
            pa[2] = __float_as_uint(pp[4]);
            pa[3] = __float_as_uint(pp[8 * PSTR + 4]);
            #pragma unroll
            for (int nt2 = 0; nt2 < 16; nt2++) {
                uint32_t b[2];
                const float* vp = Vs_ + (8 * k2 + t) * VSTR + nt2 * 8 + g;
                b[0] = __float_as_uint(vp[0]);
                b[1] = __float_as_uint(vp[4 * VSTR]);
                mma_tf32(oacc[nt2], pa, b);
            }
        }
        __syncthreads();  // done reading this stage before it's refilled
    }

    // ---- epilogue: normalize + tf32-round + store (B,S,E) ----
    const float ia = 1.0f / l_a, ib = 1.0f / l_b;
    const int b = bh / HH, h = bh % HH;
    const int rowa = q0 + warp * 16 + g, rowb = rowa + 8;
    float* opa = AO + ((size_t)(b * SS + rowa)) * EE + h * DD;
    float* opb = AO + ((size_t)(b * SS + rowb)) * EE + h * DD;
    #pragma unroll
    for (int nt2 = 0; nt2 < 16; nt2++) {
        int cl = nt2 * 8 + 2 * t;
        float2 v0, v1;
        v0.x = to_tf32(oacc[nt2][0] * ia); v0.y = to_tf32(oacc[nt2][1] * ia);
        v1.x = to_tf32(oacc[nt2][2] * ib); v1.y = to_tf32(oacc[nt2][3] * ib);
        *(float2*)(opa + cl) = v0;
        *(float2*)(opb + cl) = v1;
    }
}

// ---------------------------------------------------------------------------
extern "C" void kernel_launch(void* const* d_in, const int* in_sizes, int n_in,
                              void* d_out, int out_size)
{
    const float* query  = (const float*)d_in[0];
    const float* key_in = (const float*)d_in[1];
    const float* value  = (const float*)d_in[2];
    const float* Wq = (const float*)d_in[3];
    const float* bq = (const float*)d_in[4];
    const float* Wk = (const float*)d_in[5];
    const float* bk = (const float*)d_in[6];
    const float* Wv = (const float*)d_in[7];
    const float* bv = (const float*)d_in[8];
    const float* Wo = (const float*)d_in[9];
    const float* bo = (const float*)d_in[10];
    float* out = (float*)d_out;

    float *qbuf, *kbuf, *vbuf, *aobuf;
    float *cq, *ck, *cv, *cWq, *cWk, *cWv, *cWo;
    cudaGetSymbolAddress((void**)&qbuf,  g_Q);
    cudaGetSymbolAddress((void**)&kbuf,  g_K);
    cudaGetSymbolAddress((void**)&vbuf,  g_V);
    cudaGetSymbolAddress((void**)&aobuf, g_AO);
    cudaGetSymbolAddress((void**)&cq,  g_cq);
    cudaGetSymbolAddress((void**)&ck,  g_ck);
    cudaGetSymbolAddress((void**)&cv,  g_cv);
    cudaGetSymbolAddress((void**)&cWq, g_cWq);
    cudaGetSymbolAddress((void**)&cWk, g_cWk);
    cudaGetSymbolAddress((void**)&cWv, g_cWv);
    cudaGetSymbolAddress((void**)&cWo, g_cWo);

    const int attn2_smem = ATTN2_SMEM_FLOATS * 4;
    cudaFuncSetAttribute(attn_tc_kernel,
                         cudaFuncAttributeMaxDynamicSharedMemorySize, attn2_smem);
    cudaFuncSetAttribute(gemm_tf32_kernel<0>,
                         cudaFuncAttributeMaxDynamicSharedMemorySize, GEMM_SMEM);
    cudaFuncSetAttribute(gemm_tf32_kernel<1>,
                         cudaFuncAttributeMaxDynamicSharedMemorySize, GEMM_SMEM);

    // 1. tf32 conversion of inputs
    const int NX4 = MM * EE / 4, NW4 = EE * EE / 4;
    cvt_tf32_kernel<<<(NX4 + 255) / 256, 256>>>(query,  cq,  NX4);
    cvt_tf32_kernel<<<(NX4 + 255) / 256, 256>>>(key_in, ck,  NX4);
    cvt_tf32_kernel<<<(NX4 + 255) / 256, 256>>>(value,  cv,  NX4);
    cvt_tf32_kernel<<<(NW4 + 255) / 256, 256>>>(Wq, cWq, NW4);
    cvt_tf32_kernel<<<(NW4 + 255) / 256, 256>>>(Wk, cWk, NW4);
    cvt_tf32_kernel<<<(NW4 + 255) / 256, 256>>>(Wv, cWv, NW4);
    cvt_tf32_kernel<<<(NW4 + 255) / 256, 256>>>(Wo, cWo, NW4);

    dim3 gblock(256);
    dim3 ggrid(EE / 128, MM / 128);  // (16, 32)

    // 2. Q/K/V projections (tf32 tensor cores) -> (B,H,S,D), tf32-rounded
    gemm_tf32_kernel<1><<<ggrid, gblock, GEMM_SMEM>>>(cq, cWq, bq, qbuf);
    gemm_tf32_kernel<1><<<ggrid, gblock, GEMM_SMEM>>>(ck, cWk, bk, kbuf);
    gemm_tf32_kernel<1><<<ggrid, gblock, GEMM_SMEM>>>(cv, cWv, bv, vbuf);

    // 3. Fused tf32 tensor-core attention -> (B,S,E) tf32-rounded
    dim3 agrid(SS / 128, BB * HH);   // (16, 32)
    attn_tc_kernel<<<agrid, dim3(256), attn2_smem>>>(qbuf, kbuf, vbuf, aobuf);

    // 4. Output projection (tf32 tensor cores) -> d_out
    gemm_tf32_kernel<0><<<ggrid, gblock, GEMM_SMEM>>>(aobuf, cWo, bo, out);
}

// round 8
// speedup vs baseline: 6.2445x; 1.6186x over previous
#include <cuda_runtime.h>
#include <cuda_fp16.h>
#include <math.h>
#include <stdint.h>

// Problem constants
#define BB 2
#define SS 2048
#define EE 2048
#define HH 16
#define DD 128
#define MM (BB*SS)

// Scratch (static __device__ — no allocation allowed)
__device__ __half g_hq[(size_t)MM*EE];     // fp16 inputs [M][K]
__device__ __half g_hk[(size_t)MM*EE];
__device__ __half g_hv[(size_t)MM*EE];
__device__ __half g_hWq[(size_t)EE*EE];    // fp16 weights transposed [N][K]
__device__ __half g_hWk[(size_t)EE*EE];
__device__ __half g_hWv[(size_t)EE*EE];
__device__ __half g_hWo[(size_t)EE*EE];
__device__ __half g_Q[(size_t)BB*HH*SS*DD];   // (B,H,S,D)
__device__ __half g_K[(size_t)BB*HH*SS*DD];   // (B,H,S,D)
__device__ __half g_Vt[(size_t)BB*HH*SS*DD];  // (B,H,D,S)  V transposed
__device__ __half g_AO[(size_t)MM*EE];        // attention out (B,S,E)

#define CP_ASYNC16(sa, gp) asm volatile("cp.async.cg.shared.global [%0], [%1], 16;\n" :: "r"(sa), "l"(gp))
#define CP_COMMIT()        asm volatile("cp.async.commit_group;\n")
#define CP_WAIT1()         asm volatile("cp.async.wait_group 1;\n")
#define CP_WAIT0()         asm volatile("cp.async.wait_group 0;\n")

__device__ __forceinline__ void mma_f16(float c[4], const uint32_t a[4],
                                        uint32_t b0, uint32_t b1)
{
    asm volatile(
        "mma.sync.aligned.m16n8k16.row.col.f32.f16.f16.f32 "
        "{%0,%1,%2,%3}, {%4,%5,%6,%7}, {%8,%9}, {%0,%1,%2,%3};\n"
        : "+f"(c[0]), "+f"(c[1]), "+f"(c[2]), "+f"(c[3])
        : "r"(a[0]), "r"(a[1]), "r"(a[2]), "r"(a[3]), "r"(b0), "r"(b1));
}

// ---------------------------------------------------------------------------
// fp32 -> fp16 conversions
// ---------------------------------------------------------------------------
__global__ void cvt_f2h(const float* __restrict__ in, __half* __restrict__ out, int n4)
{
    int i = blockIdx.x * blockDim.x + threadIdx.x;
    if (i < n4) {
        float4 v = ((const float4*)in)[i];
        ((__half2*)out)[2 * i]     = __floats2half2_rn(v.x, v.y);
        ((__half2*)out)[2 * i + 1] = __floats2half2_rn(v.z, v.w);
    }
}

// W [K][N] fp32 -> Wt [N][K] fp16 (tiled transpose)
__global__ void cvt_trans_f2h(const float* __restrict__ W, __half* __restrict__ Wt)
{
    __shared__ float t[32][33];
    const int n0 = blockIdx.x * 32, k0 = blockIdx.y * 32;
    const int tx = threadIdx.x, ty = threadIdx.y;
    #pragma unroll
    for (int j = 0; j < 32; j += 8)
        t[ty + j][tx] = W[(size_t)(k0 + ty + j) * EE + n0 + tx];
    __syncthreads();
    #pragma unroll
    for (int j = 0; j < 32; j += 8)
        Wt[(size_t)(n0 + ty + j) * EE + k0 + tx] = __float2half_rn(t[tx][ty + j]);
}

// ---------------------------------------------------------------------------
// fp16 tensor-core GEMM: Y = X[M,K] * Wt[N,K]^T + bias
// MODE 0: Y fp32 row-major [M,N]
// MODE 1: Y fp16 (B,H,S,D), head = blockIdx.x
// MODE 2: Y fp16 (B,H,D,S)  (transposed per head, for V)
// Block 128x128, BK=32, 256 thr (8 warps 2x4), warp tile 64x32, mma m16n8k16.
// ---------------------------------------------------------------------------
#define BKH 32
#define XSTRH 40   // 32+8 halves
#define GEMMH_SMEM (2 * 2 * 128 * XSTRH * 2)   // X + W, 2 stages, bytes

template<int MODE>
__global__ __launch_bounds__(256, 2)
void gemm_h(const __half* __restrict__ X, const __half* __restrict__ Wt,
            const float* __restrict__ bias, void* __restrict__ Yv)
{
    extern __shared__ __half smg[];
    __half* Xs = smg;                       // [2][128][XSTRH]
    __half* Ws = smg + 2 * 128 * XSTRH;     // [2][128][XSTRH]

    const int tid  = threadIdx.x;
    const int lane = tid & 31;
    const int warp = tid >> 5;
    const int g = lane >> 2, t = lane & 3;
    const int wm = (warp >> 2) * 64;
    const int wn = (warp & 3) * 32;
    const int m0 = blockIdx.y * 128, n0 = blockIdx.x * 128;

    float acc[4][4][4];
    #pragma unroll
    for (int mi = 0; mi < 4; mi++)
        #pragma unroll
        for (int ni = 0; ni < 4; ni++)
            #pragma unroll
            for (int r = 0; r < 4; r++) acc[mi][ni][r] = 0.f;

    auto issue = [&](int stage, int k0) {
        __half* xs = Xs + stage * 128 * XSTRH;
        __half* ws = Ws + stage * 128 * XSTRH;
        #pragma unroll
        for (int j = 0; j < 2; j++) {
            int c = tid + j * 256;          // 0..511
            int r = c >> 2, ch = c & 3;     // 128 rows x 4 chunks (32 halves)
            uint32_t sa = (uint32_t)__cvta_generic_to_shared(xs + r * XSTRH + ch * 8);
            CP_ASYNC16(sa, X + (size_t)(m0 + r) * EE + k0 + ch * 8);
            uint32_t sb = (uint32_t)__cvta_generic_to_shared(ws + r * XSTRH + ch * 8);
            CP_ASYNC16(sb, Wt + (size_t)(n0 + r) * EE + k0 + ch * 8);
        }
    };

    issue(0, 0);
    CP_COMMIT();

    const int NT = EE / BKH;  // 64
    for (int it = 0; it < NT; it++) {
        if (it + 1 < NT) {
            issue((it + 1) & 1, (it + 1) * BKH);
            CP_COMMIT();
            CP_WAIT1();
        } else {
            CP_WAIT0();
        }
        __syncthreads();

        const __half* xs = Xs + (it & 1) * 128 * XSTRH;
        const __half* ws = Ws + (it & 1) * 128 * XSTRH;

        #pragma unroll
        for (int ks = 0; ks < 2; ks++) {
            uint32_t a[4][4], b[4][2];
            #pragma unroll
            for (int mi = 0; mi < 4; mi++) {
                const __half* ap = xs + (wm + mi * 16 + g) * XSTRH + 16 * ks + 2 * t;
                a[mi][0] = *(const uint32_t*)ap;
                a[mi][1] = *(const uint32_t*)(ap + 8 * XSTRH);
                a[mi][2] = *(const uint32_t*)(ap + 8);
                a[mi][3] = *(const uint32_t*)(ap + 8 * XSTRH + 8);
            }
            #pragma unroll
            for (int ni = 0; ni < 4; ni++) {
                const __half* bp = ws + (wn + ni * 8 + g) * XSTRH + 16 * ks + 2 * t;
                b[ni][0] = *(const uint32_t*)bp;
                b[ni][1] = *(const uint32_t*)(bp + 8);
            }
            #pragma unroll
            for (int mi = 0; mi < 4; mi++)
                #pragma unroll
                for (int ni = 0; ni < 4; ni++)
                    mma_f16(acc[mi][ni], a[mi], b[ni][0], b[ni][1]);
        }
        __syncthreads();
    }

    // Epilogue
    #pragma unroll
    for (int mi = 0; mi < 4; mi++) {
        #pragma unroll
        for (int ni = 0; ni < 4; ni++) {
            int row = m0 + wm + mi * 16 + g;
            int cl  = wn + ni * 8 + 2 * t;
            int n   = n0 + cl;
            float bx = bias[n], by = bias[n + 1];
            float c00 = acc[mi][ni][0] + bx, c01 = acc[mi][ni][1] + by;
            float c10 = acc[mi][ni][2] + bx, c11 = acc[mi][ni][3] + by;
            if (MODE == 0) {
                float* Y = (float*)Yv;
                *(float2*)(Y + (size_t)row * EE + n)       = make_float2(c00, c01);
                *(float2*)(Y + (size_t)(row + 8) * EE + n) = make_float2(c10, c11);
            } else if (MODE == 1) {
                __half* Y = (__half*)Yv;
                int b0r = row >> 11, s = row & (SS - 1);
                int s2 = (row + 8) & (SS - 1);
                __half* base = Y + ((size_t)(b0r * HH + blockIdx.x) * SS + s) * DD + cl;
                *(__half2*)base = __floats2half2_rn(c00, c01);
                __half* base2 = Y + ((size_t)(b0r * HH + blockIdx.x) * SS + s2) * DD + cl;
                *(__half2*)base2 = __floats2half2_rn(c10, c11);
            } else {
                // (B,H,D,S): columns cl and cl+1
                __half* Y = (__half*)Yv;
                int b0r = row >> 11, s = row & (SS - 1);
                int s2 = (row + 8) & (SS - 1);
                __half* colp = Y + ((size_t)(b0r * HH + blockIdx.x) * DD + cl) * SS;
                colp[s]  = __float2half_rn(c00);
                colp[s2] = __float2half_rn(c10);
                __half* colp2 = colp + SS;
                colp2[s]  = __float2half_rn(c01);
                colp2[s2] = __float2half_rn(c11);
            }
        }
    }
}

// ---------------------------------------------------------------------------
// fp16 tensor-core flash attention
// CTA: 256 thr / 8 warps; Q tile 128 (warp w: rows 16w..16w+15); KV tile 64.
// Q in register fragments; K (B,H,S,D) and Vt (B,H,D,S) double-buffered smem.
// ---------------------------------------------------------------------------
#define TKH 64
#define KSTRH 136
#define VSTRH 72
#define PSTRH 72
#define ATTNH_SMEM ((2*TKH*KSTRH + 2*DD*VSTRH + 8*16*PSTRH) * 2)

__global__ __launch_bounds__(256, 1)
void attn_h(const __half* __restrict__ Q, const __half* __restrict__ K,
            const __half* __restrict__ Vt, __half* __restrict__ AO)
{
    extern __shared__ __half smh[];
    __half* Kb = smh;                       // [2][TKH][KSTRH]
    __half* Vb = smh + 2 * TKH * KSTRH;     // [2][DD][VSTRH]
    __half* Pw = Vb + 2 * DD * VSTRH;       // [8][16][PSTRH]

    const int tid  = threadIdx.x;
    const int lane = tid & 31;
    const int warp = tid >> 5;
    const int g = lane >> 2, t = lane & 3;
    const int bh = blockIdx.y;
    const int q0 = blockIdx.x * 128;

    const __half* Qg = Q + ((size_t)bh * SS + q0) * DD;
    const __half* Kg = K + (size_t)bh * SS * DD;
    const __half* Vg = Vt + (size_t)bh * DD * SS;   // [d][s]

    // ---- stage Q (128 rows x 128 halves = 2048 chunks) into Kb, then regs ----
    #pragma unroll
    for (int j = 0; j < 8; j++) {
        int c = tid + j * 256;              // 0..2047
        int r = c >> 4, ch = c & 15;
        uint32_t sa = (uint32_t)__cvta_generic_to_shared(Kb + r * KSTRH + ch * 8);
        CP_ASYNC16(sa, Qg + (size_t)r * DD + ch * 8);
    }
    CP_COMMIT(); CP_WAIT0();
    __syncthreads();

    uint32_t qa[8][4];
    {
        const __half* qp = Kb + (warp * 16 + g) * KSTRH;
        #pragma unroll
        for (int ks = 0; ks < 8; ks++) {
            qa[ks][0] = *(const uint32_t*)(qp + 16 * ks + 2 * t);
            qa[ks][1] = *(const uint32_t*)(qp + 8 * KSTRH + 16 * ks + 2 * t);
            qa[ks][2] = *(const uint32_t*)(qp + 16 * ks + 2 * t + 8);
            qa[ks][3] = *(const uint32_t*)(qp + 8 * KSTRH + 16 * ks + 2 * t + 8);
        }
    }
    __syncthreads();

    float oacc[16][4];
    #pragma unroll
    for (int n = 0; n < 16; n++)
        #pragma unroll
        for (int r = 0; r < 4; r++) oacc[n][r] = 0.f;
    float m_a = -1e30f, m_b = -1e30f, l_a = 0.f, l_b = 0.f;

    const float scale = 0.08838834764831845f;  // 1/sqrt(128)

    auto load_kv = [&](int stage, int kt) {
        __half* ks_ = Kb + stage * TKH * KSTRH;
        __half* vs_ = Vb + stage * DD * VSTRH;
        // K: 64 rows x 128 halves = 1024 chunks  (FIXED: was j<2 with 64-half rows)
        #pragma unroll
        for (int j = 0; j < 4; j++) {
            int c = tid + j * 256;          // 0..1023
            int r = c >> 4, ch = c & 15;    // row 0..63, chunk 0..15
            uint32_t sk = (uint32_t)__cvta_generic_to_shared(ks_ + r * KSTRH + ch * 8);
            CP_ASYNC16(sk, Kg + (size_t)(kt + r) * DD + ch * 8);
        }
        // Vt: 128 d-rows x 64 s-halves = 1024 chunks
        #pragma unroll
        for (int j = 0; j < 4; j++) {
            int c = tid + j * 256;          // 0..1023
            int r = c >> 3, ch = c & 7;     // row 0..127, chunk 0..7
            uint32_t sv = (uint32_t)__cvta_generic_to_shared(vs_ + r * VSTRH + ch * 8);
            CP_ASYNC16(sv, Vg + (size_t)r * SS + kt + ch * 8);
        }
    };

    load_kv(0, 0);
    CP_COMMIT();

    const int NTILES = SS / TKH;  // 32
    for (int it = 0; it < NTILES; it++) {
        if (it + 1 < NTILES) {
            load_kv((it + 1) & 1, (it + 1) * TKH);
            CP_COMMIT();
            CP_WAIT1();
        } else {
            CP_WAIT0();
        }
        __syncthreads();

        const __half* ks_ = Kb + (it & 1) * TKH * KSTRH;
        const __half* vs_ = Vb + (it & 1) * DD * VSTRH;

        // ---- S = Q K^T ----
        float sacc[8][4];
        #pragma unroll
        for (int n = 0; n < 8; n++)
            #pragma unroll
            for (int r = 0; r < 4; r++) sacc[n][r] = 0.f;

        #pragma unroll
        for (int ks = 0; ks < 8; ks++) {
            #pragma unroll
            for (int nt = 0; nt < 8; nt++) {
                const __half* bp = ks_ + (nt * 8 + g) * KSTRH + 16 * ks + 2 * t;
                uint32_t b0 = *(const uint32_t*)bp;
                uint32_t b1 = *(const uint32_t*)(bp + 8);
                mma_f16(sacc[nt], qa[ks], b0, b1);
            }
        }

        // ---- online softmax (rows g, g+8; 4 lanes/row via xor 1,2) ----
        float mxa = -1e30f, mxb = -1e30f;
        #pragma unroll
        for (int nt = 0; nt < 8; nt++) {
            sacc[nt][0] *= scale; sacc[nt][1] *= scale;
            sacc[nt][2] *= scale; sacc[nt][3] *= scale;
            mxa = fmaxf(mxa, fmaxf(sacc[nt][0], sacc[nt][1]));
            mxb = fmaxf(mxb, fmaxf(sacc[nt][2], sacc[nt][3]));
        }
        mxa = fmaxf(mxa, __shfl_xor_sync(0xffffffffu, mxa, 1));
        mxa = fmaxf(mxa, __shfl_xor_sync(0xffffffffu, mxa, 2));
        mxb = fmaxf(mxb, __shfl_xor_sync(0xffffffffu, mxb, 1));
        mxb = fmaxf(mxb, __shfl_xor_sync(0xffffffffu, mxb, 2));

        float mna = fmaxf(m_a, mxa), mnb = fmaxf(m_b, mxb);
        float ca = __expf(m_a - mna), cb = __expf(m_b - mnb);
        m_a = mna; m_b = mnb;

        float ra = 0.f, rb = 0.f;
        __half* pw = Pw + warp * 16 * PSTRH;
        #pragma unroll
        for (int nt = 0; nt < 8; nt++) {
            __half h0 = __float2half_rn(__expf(sacc[nt][0] - mna));
            __half h1 = __float2half_rn(__expf(sacc[nt][1] - mna));
            __half h2 = __float2half_rn(__expf(sacc[nt][2] - mnb));
            __half h3 = __float2half_rn(__expf(sacc[nt][3] - mnb));
            ra += __half2float(h0) + __half2float(h1);
            rb += __half2float(h2) + __half2float(h3);
            __half2 pa01; pa01.x = h0; pa01.y = h1;
            __half2 pa23; pa23.x = h2; pa23.y = h3;
            *(__half2*)&pw[g * PSTRH + nt * 8 + 2 * t]       = pa01;
            *(__half2*)&pw[(g + 8) * PSTRH + nt * 8 + 2 * t] = pa23;
        }
        ra += __shfl_xor_sync(0xffffffffu, ra, 1);
        ra += __shfl_xor_sync(0xffffffffu, ra, 2);
        rb += __shfl_xor_sync(0xffffffffu, rb, 1);
        rb += __shfl_xor_sync(0xffffffffu, rb, 2);
        l_a = l_a * ca + ra;
        l_b = l_b * cb + rb;

        #pragma unroll
        for (int n = 0; n < 16; n++) {
            oacc[n][0] *= ca; oacc[n][1] *= ca;
            oacc[n][2] *= cb; oacc[n][3] *= cb;
        }
        __syncwarp();  // P visible within warp

        // ---- O += P V ----
        #pragma unroll
        for (int k2 = 0; k2 < 4; k2++) {
            uint32_t pa[4];
            const __half* pp = pw + g * PSTRH + 16 * k2 + 2 * t;
            pa[0] = *(const uint32_t*)pp;
            pa[1] = *(const uint32_t*)(pp + 8 * PSTRH);
            pa[2] = *(const uint32_t*)(pp + 8);
            pa[3] = *(const uint32_t*)(pp + 8 * PSTRH + 8);
            #pragma unroll
            for (int nt2 = 0; nt2 < 16; nt2++) {
                const __half* vp = vs_ + (nt2 * 8 + g) * VSTRH + 16 * k2 + 2 * t;
                uint32_t b0 = *(const uint32_t*)vp;
                uint32_t b1 = *(const uint32_t*)(vp + 8);
                mma_f16(oacc[nt2], pa, b0, b1);
            }
        }
        __syncthreads();
    }

    // ---- epilogue: normalize + store AO fp16 (B,S,E) ----
    const float ia = 1.0f / l_a, ib = 1.0f / l_b;
    const int b = bh / HH, h = bh % HH;
    const int rowa = q0 + warp * 16 + g, rowb = rowa + 8;
    __half* opa = AO + ((size_t)(b * SS + rowa)) * EE + h * DD;
    __half* opb = AO + ((size_t)(b * SS + rowb)) * EE + h * DD;
    #pragma unroll
    for (int nt2 = 0; nt2 < 16; nt2++) {
        int cl = nt2 * 8 + 2 * t;
        *(__half2*)(opa + cl) = __floats2half2_rn(oacc[nt2][0] * ia, oacc[nt2][1] * ia);
        *(__half2*)(opb + cl) = __floats2half2_rn(oacc[nt2][2] * ib, oacc[nt2][3] * ib);
    }
}

// ---------------------------------------------------------------------------
extern "C" void kernel_launch(void* const* d_in, const int* in_sizes, int n_in,
                              void* d_out, int out_size)
{
    const float* query  = (const float*)d_in[0];
    const float* key_in = (const float*)d_in[1];
    const float* value  = (const float*)d_in[2];
    const float* Wq = (const float*)d_in[3];
    const float* bq = (const float*)d_in[4];
    const float* Wk = (const float*)d_in[5];
    const float* bk = (const float*)d_in[6];
    const float* Wv = (const float*)d_in[7];
    const float* bv = (const float*)d_in[8];
    const float* Wo = (const float*)d_in[9];
    const float* bo = (const float*)d_in[10];
    float* out = (float*)d_out;

    __half *hq, *hk, *hv, *hWq, *hWk, *hWv, *hWo;
    __half *qbuf, *kbuf, *vtbuf, *aobuf;
    cudaGetSymbolAddress((void**)&hq,  g_hq);
    cudaGetSymbolAddress((void**)&hk,  g_hk);
    cudaGetSymbolAddress((void**)&hv,  g_hv);
    cudaGetSymbolAddress((void**)&hWq, g_hWq);
    cudaGetSymbolAddress((void**)&hWk, g_hWk);
    cudaGetSymbolAddress((void**)&hWv, g_hWv);
    cudaGetSymbolAddress((void**)&hWo, g_hWo);
    cudaGetSymbolAddress((void**)&qbuf,  g_Q);
    cudaGetSymbolAddress((void**)&kbuf,  g_K);
    cudaGetSymbolAddress((void**)&vtbuf, g_Vt);
    cudaGetSymbolAddress((void**)&aobuf, g_AO);

    cudaFuncSetAttribute(attn_h,
                         cudaFuncAttributeMaxDynamicSharedMemorySize, ATTNH_SMEM);
    cudaFuncSetAttribute(gemm_h<0>,
                         cudaFuncAttributeMaxDynamicSharedMemorySize, GEMMH_SMEM);
    cudaFuncSetAttribute(gemm_h<1>,
                         cudaFuncAttributeMaxDynamicSharedMemorySize, GEMMH_SMEM);
    cudaFuncSetAttribute(gemm_h<2>,
                         cudaFuncAttributeMaxDynamicSharedMemorySize, GEMMH_SMEM);

    // 1. fp16 conversions
    const int NX4 = MM * EE / 4;
    cvt_f2h<<<(NX4 + 255) / 256, 256>>>(query,  hq, NX4);
    cvt_f2h<<<(NX4 + 255) / 256, 256>>>(key_in, hk, NX4);
    cvt_f2h<<<(NX4 + 255) / 256, 256>>>(value,  hv, NX4);
    dim3 tgrid(EE / 32, EE / 32), tblock(32, 8);
    cvt_trans_f2h<<<tgrid, tblock>>>(Wq, hWq);
    cvt_trans_f2h<<<tgrid, tblock>>>(Wk, hWk);
    cvt_trans_f2h<<<tgrid, tblock>>>(Wv, hWv);
    cvt_trans_f2h<<<tgrid, tblock>>>(Wo, hWo);

    dim3 gblock(256);
    dim3 ggrid(EE / 128, MM / 128);  // (16, 32)

    // 2. Projections (fp16 tensor cores)
    gemm_h<1><<<ggrid, gblock, GEMMH_SMEM>>>(hq, hWq, bq, qbuf);
    gemm_h<1><<<ggrid, gblock, GEMMH_SMEM>>>(hk, hWk, bk, kbuf);
    gemm_h<2><<<ggrid, gblock, GEMMH_SMEM>>>(hv, hWv, bv, vtbuf);

    // 3. Fused fp16 tensor-core attention -> (B,S,E) fp16
    dim3 agrid(SS / 128, BB * HH);   // (16, 32)
    attn_h<<<agrid, gblock, ATTNH_SMEM>>>(qbuf, kbuf, vtbuf, aobuf);

    // 4. Output projection -> d_out fp32
    gemm_h<0><<<ggrid, gblock, GEMMH_SMEM>>>(aobuf, hWo, bo, out);
}

// round 9
// speedup vs baseline: 6.6479x; 1.0646x over previous
#include <cuda_runtime.h>
#include <cuda_fp16.h>
#include <math.h>
#include <stdint.h>

// Problem constants
#define BB 2
#define SS 2048
#define EE 2048
#define HH 16
#define DD 128
#define MM (BB*SS)

// Scratch (static __device__ — no allocation allowed)
__device__ __half g_hq[(size_t)MM*EE];     // fp16 inputs [M][K]
__device__ __half g_hk[(size_t)MM*EE];
__device__ __half g_hv[(size_t)MM*EE];
__device__ __half g_hWq[(size_t)EE*EE];    // fp16 weights transposed [N][K]
__device__ __half g_hWk[(size_t)EE*EE];
__device__ __half g_hWv[(size_t)EE*EE];
__device__ __half g_hWo[(size_t)EE*EE];
__device__ __half g_Q[(size_t)BB*HH*SS*DD];   // (B,H,S,D)
__device__ __half g_K[(size_t)BB*HH*SS*DD];   // (B,H,S,D)
__device__ __half g_Vt[(size_t)BB*HH*SS*DD];  // (B,H,D,S)  V transposed
__device__ __half g_AO[(size_t)MM*EE];        // attention out (B,S,E)

#define CP_ASYNC16(sa, gp) asm volatile("cp.async.cg.shared.global [%0], [%1], 16;\n" :: "r"(sa), "l"(gp))
#define CP_COMMIT()        asm volatile("cp.async.commit_group;\n")
#define CP_WAIT1()         asm volatile("cp.async.wait_group 1;\n")
#define CP_WAIT0()         asm volatile("cp.async.wait_group 0;\n")

#define LDSM_X4(r0, r1, r2, r3, addr) \
    asm volatile("ldmatrix.sync.aligned.m8n8.x4.shared.b16 {%0,%1,%2,%3}, [%4];\n" \
                 : "=r"(r0), "=r"(r1), "=r"(r2), "=r"(r3) : "r"(addr))

__device__ __forceinline__ void mma_f16(float c[4], const uint32_t a[4],
                                        uint32_t b0, uint32_t b1)
{
    asm volatile(
        "mma.sync.aligned.m16n8k16.row.col.f32.f16.f16.f32 "
        "{%0,%1,%2,%3}, {%4,%5,%6,%7}, {%8,%9}, {%0,%1,%2,%3};\n"
        : "+f"(c[0]), "+f"(c[1]), "+f"(c[2]), "+f"(c[3])
        : "r"(a[0]), "r"(a[1]), "r"(a[2]), "r"(a[3]), "r"(b0), "r"(b1));
}

// Lane selectors for ldmatrix.x4 address generation
//   A-type (16x16, a0..a3): row = lane&15, colH = (lane>>4)*8
//   B-type (two n8k16 frags): row = (lane&7) + ((lane>>4)<<3), colH = ((lane>>3)&1)*8
__device__ __forceinline__ int lrow_a(int lane) { return lane & 15; }
__device__ __forceinline__ int lcol_a(int lane) { return (lane >> 4) * 8; }
__device__ __forceinline__ int lrow_b(int lane) { return (lane & 7) + ((lane >> 4) << 3); }
__device__ __forceinline__ int lcol_b(int lane) { return ((lane >> 3) & 1) * 8; }

// ---------------------------------------------------------------------------
// fp32 -> fp16 conversions
// ---------------------------------------------------------------------------
__global__ void cvt_f2h(const float* __restrict__ in, __half* __restrict__ out, int n4)
{
    int i = blockIdx.x * blockDim.x + threadIdx.x;
    if (i < n4) {
        float4 v = ((const float4*)in)[i];
        ((__half2*)out)[2 * i]     = __floats2half2_rn(v.x, v.y);
        ((__half2*)out)[2 * i + 1] = __floats2half2_rn(v.z, v.w);
    }
}

// W [K][N] fp32 -> Wt [N][K] fp16 (tiled transpose)
__global__ void cvt_trans_f2h(const float* __restrict__ W, __half* __restrict__ Wt)
{
    __shared__ float t[32][33];
    const int n0 = blockIdx.x * 32, k0 = blockIdx.y * 32;
    const int tx = threadIdx.x, ty = threadIdx.y;
    #pragma unroll
    for (int j = 0; j < 32; j += 8)
        t[ty + j][tx] = W[(size_t)(k0 + ty + j) * EE + n0 + tx];
    __syncthreads();
    #pragma unroll
    for (int j = 0; j < 32; j += 8)
        Wt[(size_t)(n0 + ty + j) * EE + k0 + tx] = __float2half_rn(t[tx][ty + j]);
}

// ---------------------------------------------------------------------------
// fp16 tensor-core GEMM: Y = X[M,K] * Wt[N,K]^T + bias
// MODE 0: fp32 [M,N]; MODE 1: fp16 (B,H,S,D); MODE 2: fp16 (B,H,D,S)
// Block 128x128, BK=32, 256 thr (8 warps 2x4), warp tile 64x32, mma m16n8k16.
// Fragments via ldmatrix.x4 (stride 40 halves -> LDSM groups 5r mod 8, bijective).
// ---------------------------------------------------------------------------
#define BKH 32
#define XSTRH 40
#define GEMMH_SMEM (2 * 2 * 128 * XSTRH * 2)

template<int MODE>
__global__ __launch_bounds__(256, 2)
void gemm_h(const __half* __restrict__ X, const __half* __restrict__ Wt,
            const float* __restrict__ bias, void* __restrict__ Yv)
{
    extern __shared__ __half smg[];
    __half* Xs = smg;                       // [2][128][XSTRH]
    __half* Ws = smg + 2 * 128 * XSTRH;     // [2][128][XSTRH]

    const int tid  = threadIdx.x;
    const int lane = tid & 31;
    const int warp = tid >> 5;
    const int g = lane >> 2, t = lane & 3;
    const int wm = (warp >> 2) * 64;
    const int wn = (warp & 3) * 32;
    const int m0 = blockIdx.y * 128, n0 = blockIdx.x * 128;

    const int ra = lrow_a(lane), ca = lcol_a(lane);
    const int rb = lrow_b(lane), cb = lcol_b(lane);

    float acc[4][4][4];
    #pragma unroll
    for (int mi = 0; mi < 4; mi++)
        #pragma unroll
        for (int ni = 0; ni < 4; ni++)
            #pragma unroll
            for (int r = 0; r < 4; r++) acc[mi][ni][r] = 0.f;

    auto issue = [&](int stage, int k0) {
        __half* xs = Xs + stage * 128 * XSTRH;
        __half* ws = Ws + stage * 128 * XSTRH;
        #pragma unroll
        for (int j = 0; j < 2; j++) {
            int c = tid + j * 256;          // 0..511
            int r = c >> 2, ch = c & 3;     // 128 rows x 4 chunks
            uint32_t sa = (uint32_t)__cvta_generic_to_shared(xs + r * XSTRH + ch * 8);
            CP_ASYNC16(sa, X + (size_t)(m0 + r) * EE + k0 + ch * 8);
            uint32_t sb = (uint32_t)__cvta_generic_to_shared(ws + r * XSTRH + ch * 8);
            CP_ASYNC16(sb, Wt + (size_t)(n0 + r) * EE + k0 + ch * 8);
        }
    };

    issue(0, 0);
    CP_COMMIT();

    const int NT = EE / BKH;  // 64
    for (int it = 0; it < NT; it++) {
        if (it + 1 < NT) {
            issue((it + 1) & 1, (it + 1) * BKH);
            CP_COMMIT();
            CP_WAIT1();
        } else {
            CP_WAIT0();
        }
        __syncthreads();

        const __half* xs = Xs + (it & 1) * 128 * XSTRH;
        const __half* ws = Ws + (it & 1) * 128 * XSTRH;

        #pragma unroll
        for (int ks = 0; ks < 2; ks++) {
            uint32_t a[4][4], b[4][2];
            #pragma unroll
            for (int mi = 0; mi < 4; mi++) {
                uint32_t ad = (uint32_t)__cvta_generic_to_shared(
                    xs + (wm + mi * 16 + ra) * XSTRH + 16 * ks + ca);
                LDSM_X4(a[mi][0], a[mi][1], a[mi][2], a[mi][3], ad);
            }
            #pragma unroll
            for (int ni2 = 0; ni2 < 2; ni2++) {
                uint32_t bd = (uint32_t)__cvta_generic_to_shared(
                    ws + (wn + ni2 * 16 + rb) * XSTRH + 16 * ks + cb);
                LDSM_X4(b[2 * ni2][0], b[2 * ni2][1],
                        b[2 * ni2 + 1][0], b[2 * ni2 + 1][1], bd);
            }
            #pragma unroll
            for (int mi = 0; mi < 4; mi++)
                #pragma unroll
                for (int ni = 0; ni < 4; ni++)
                    mma_f16(acc[mi][ni], a[mi], b[ni][0], b[ni][1]);
        }
        __syncthreads();
    }

    // Epilogue
    #pragma unroll
    for (int mi = 0; mi < 4; mi++) {
        #pragma unroll
        for (int ni = 0; ni < 4; ni++) {
            int row = m0 + wm + mi * 16 + g;
            int cl  = wn + ni * 8 + 2 * t;
            int n   = n0 + cl;
            float bx = bias[n], by = bias[n + 1];
            float c00 = acc[mi][ni][0] + bx, c01 = acc[mi][ni][1] + by;
            float c10 = acc[mi][ni][2] + bx, c11 = acc[mi][ni][3] + by;
            if (MODE == 0) {
                float* Y = (float*)Yv;
                *(float2*)(Y + (size_t)row * EE + n)       = make_float2(c00, c01);
                *(float2*)(Y + (size_t)(row + 8) * EE + n) = make_float2(c10, c11);
            } else if (MODE == 1) {
                __half* Y = (__half*)Yv;
                int b0r = row >> 11, s = row & (SS - 1);
                int s2 = (row + 8) & (SS - 1);
                __half* base = Y + ((size_t)(b0r * HH + blockIdx.x) * SS + s) * DD + cl;
                *(__half2*)base = __floats2half2_rn(c00, c01);
                __half* base2 = Y + ((size_t)(b0r * HH + blockIdx.x) * SS + s2) * DD + cl;
                *(__half2*)base2 = __floats2half2_rn(c10, c11);
            } else {
                __half* Y = (__half*)Yv;
                int b0r = row >> 11, s = row & (SS - 1);
                int s2 = (row + 8) & (SS - 1);
                __half* colp = Y + ((size_t)(b0r * HH + blockIdx.x) * DD + cl) * SS;
                colp[s]  = __float2half_rn(c00);
                colp[s2] = __float2half_rn(c10);
                __half* colp2 = colp + SS;
                colp2[s]  = __float2half_rn(c01);
                colp2[s2] = __float2half_rn(c11);
            }
        }
    }
}

// ---------------------------------------------------------------------------
// fp16 tensor-core flash attention (fragments via ldmatrix)
// CTA: 256 thr / 8 warps; Q tile 128 (warp w: rows 16w..16w+15); KV tile 64.
// Strides (halves): K 136 (group r mod 8), Vt 72 (r mod 8), P 72 — conflict-free.
// ---------------------------------------------------------------------------
#define TKH 64
#define KSTRH 136
#define VSTRH 72
#define PSTRH 72
#define ATTNH_SMEM ((2*TKH*KSTRH + 2*DD*VSTRH + 8*16*PSTRH) * 2)

__global__ __launch_bounds__(256, 1)
void attn_h(const __half* __restrict__ Q, const __half* __restrict__ K,
            const __half* __restrict__ Vt, __half* __restrict__ AO)
{
    extern __shared__ __half smh[];
    __half* Kb = smh;                       // [2][TKH][KSTRH]
    __half* Vb = smh + 2 * TKH * KSTRH;     // [2][DD][VSTRH]
    __half* Pw = Vb + 2 * DD * VSTRH;       // [8][16][PSTRH]

    const int tid  = threadIdx.x;
    const int lane = tid & 31;
    const int warp = tid >> 5;
    const int g = lane >> 2, t = lane & 3;
    const int bh = blockIdx.y;
    const int q0 = blockIdx.x * 128;

    const int ra = lrow_a(lane), ca = lcol_a(lane);
    const int rb = lrow_b(lane), cb = lcol_b(lane);

    const __half* Qg = Q + ((size_t)bh * SS + q0) * DD;
    const __half* Kg = K + (size_t)bh * SS * DD;
    const __half* Vg = Vt + (size_t)bh * DD * SS;   // [d][s]

    // ---- stage Q (128 rows x 128 halves) into Kb, then to regs via ldmatrix ----
    #pragma unroll
    for (int j = 0; j < 8; j++) {
        int c = tid + j * 256;              // 0..2047
        int r = c >> 4, ch = c & 15;
        uint32_t sa = (uint32_t)__cvta_generic_to_shared(Kb + r * KSTRH + ch * 8);
        CP_ASYNC16(sa, Qg + (size_t)r * DD + ch * 8);
    }
    CP_COMMIT(); CP_WAIT0();
    __syncthreads();

    uint32_t qa[8][4];
    #pragma unroll
    for (int ks = 0; ks < 8; ks++) {
        uint32_t ad = (uint32_t)__cvta_generic_to_shared(
            Kb + (warp * 16 + ra) * KSTRH + 16 * ks + ca);
        LDSM_X4(qa[ks][0], qa[ks][1], qa[ks][2], qa[ks][3], ad);
    }
    __syncthreads();

    float oacc[16][4];
    #pragma unroll
    for (int n = 0; n < 16; n++)
        #pragma unroll
        for (int r = 0; r < 4; r++) oacc[n][r] = 0.f;
    float m_a = -1e30f, m_b = -1e30f, l_a = 0.f, l_b = 0.f;

    const float scale = 0.08838834764831845f;  // 1/sqrt(128)

    auto load_kv = [&](int stage, int kt) {
        __half* ks_ = Kb + stage * TKH * KSTRH;
        __half* vs_ = Vb + stage * DD * VSTRH;
        #pragma unroll
        for (int j = 0; j < 4; j++) {       // K: 64 rows x 16 chunks
            int c = tid + j * 256;
            int r = c >> 4, ch = c & 15;
            uint32_t sk = (uint32_t)__cvta_generic_to_shared(ks_ + r * KSTRH + ch * 8);
            CP_ASYNC16(sk, Kg + (size_t)(kt + r) * DD + ch * 8);
        }
        #pragma unroll
        for (int j = 0; j < 4; j++) {       // Vt: 128 d-rows x 8 chunks
            int c = tid + j * 256;
            int r = c >> 3, ch = c & 7;
            uint32_t sv = (uint32_t)__cvta_generic_to_shared(vs_ + r * VSTRH + ch * 8);
            CP_ASYNC16(sv, Vg + (size_t)r * SS + kt + ch * 8);
        }
    };

    load_kv(0, 0);
    CP_COMMIT();

    const int NTILES = SS / TKH;  // 32
    for (int it = 0; it < NTILES; it++) {
        if (it + 1 < NTILES) {
            load_kv((it + 1) & 1, (it + 1) * TKH);
            CP_COMMIT();
            CP_WAIT1();
        } else {
            CP_WAIT0();
        }
        __syncthreads();

        const __half* ks_ = Kb + (it & 1) * TKH * KSTRH;
        const __half* vs_ = Vb + (it & 1) * DD * VSTRH;

        // ---- S = Q K^T ----
        float sacc[8][4];
        #pragma unroll
        for (int n = 0; n < 8; n++)
            #pragma unroll
            for (int r = 0; r < 4; r++) sacc[n][r] = 0.f;

        #pragma unroll
        for (int ks = 0; ks < 8; ks++) {
            uint32_t b[8][2];
            #pragma unroll
            for (int ni2 = 0; ni2 < 4; ni2++) {
                uint32_t bd = (uint32_t)__cvta_generic_to_shared(
                    ks_ + (ni2 * 16 + rb) * KSTRH + 16 * ks + cb);
                LDSM_X4(b[2 * ni2][0], b[2 * ni2][1],
                        b[2 * ni2 + 1][0], b[2 * ni2 + 1][1], bd);
            }
            #pragma unroll
            for (int nt = 0; nt < 8; nt++)
                mma_f16(sacc[nt], qa[ks], b[nt][0], b[nt][1]);
        }

        // ---- online softmax (rows g, g+8; 4 lanes/row via xor 1,2) ----
        float mxa = -1e30f, mxb = -1e30f;
        #pragma unroll
        for (int nt = 0; nt < 8; nt++) {
            sacc[nt][0] *= scale; sacc[nt][1] *= scale;
            sacc[nt][2] *= scale; sacc[nt][3] *= scale;
            mxa = fmaxf(mxa, fmaxf(sacc[nt][0], sacc[nt][1]));
            mxb = fmaxf(mxb, fmaxf(sacc[nt][2], sacc[nt][3]));
        }
        mxa = fmaxf(mxa, __shfl_xor_sync(0xffffffffu, mxa, 1));
        mxa = fmaxf(mxa, __shfl_xor_sync(0xffffffffu, mxa, 2));
        mxb = fmaxf(mxb, __shfl_xor_sync(0xffffffffu, mxb, 1));
        mxb = fmaxf(mxb, __shfl_xor_sync(0xffffffffu, mxb, 2));

        float mna = fmaxf(m_a, mxa), mnb = fmaxf(m_b, mxb);
        float ca2 = __expf(m_a - mna), cb2 = __expf(m_b - mnb);
        m_a = mna; m_b = mnb;

        float ra2 = 0.f, rb2 = 0.f;
        __half* pw = Pw + warp * 16 * PSTRH;
        #pragma unroll
        for (int nt = 0; nt < 8; nt++) {
            __half h0 = __float2half_rn(__expf(sacc[nt][0] - mna));
            __half h1 = __float2half_rn(__expf(sacc[nt][1] - mna));
            __half h2 = __float2half_rn(__expf(sacc[nt][2] - mnb));
            __half h3 = __float2half_rn(__expf(sacc[nt][3] - mnb));
            ra2 += __half2float(h0) + __half2float(h1);
            rb2 += __half2float(h2) + __half2float(h3);
            __half2 pa01; pa01.x = h0; pa01.y = h1;
            __half2 pa23; pa23.x = h2; pa23.y = h3;
            *(__half2*)&pw[g * PSTRH + nt * 8 + 2 * t]       = pa01;
            *(__half2*)&pw[(g + 8) * PSTRH + nt * 8 + 2 * t] = pa23;
        }
        ra2 += __shfl_xor_sync(0xffffffffu, ra2, 1);
        ra2 += __shfl_xor_sync(0xffffffffu, ra2, 2);
        rb2 += __shfl_xor_sync(0xffffffffu, rb2, 1);
        rb2 += __shfl_xor_sync(0xffffffffu, rb2, 2);
        l_a = l_a * ca2 + ra2;
        l_b = l_b * cb2 + rb2;

        #pragma unroll
        for (int n = 0; n < 16; n++) {
            oacc[n][0] *= ca2; oacc[n][1] *= ca2;
            oacc[n][2] *= cb2; oacc[n][3] *= cb2;
        }
        __syncwarp();  // P visible within warp

        // ---- O += P V ----
        #pragma unroll
        for (int k2 = 0; k2 < 4; k2++) {
            uint32_t pa[4];
            uint32_t pd = (uint32_t)__cvta_generic_to_shared(
                pw + ra * PSTRH + 16 * k2 + ca);
            LDSM_X4(pa[0], pa[1], pa[2], pa[3], pd);
            #pragma unroll
            for (int ni2 = 0; ni2 < 8; ni2++) {
                uint32_t b[4];
                uint32_t bd = (uint32_t)__cvta_generic_to_shared(
                    vs_ + (ni2 * 16 + rb) * VSTRH + 16 * k2 + cb);
                LDSM_X4(b[0], b[1], b[2], b[3], bd);
                mma_f16(oacc[2 * ni2],     pa, b[0], b[1]);
                mma_f16(oacc[2 * ni2 + 1], pa, b[2], b[3]);
            }
        }
        __syncthreads();
    }

    // ---- epilogue: normalize + store AO fp16 (B,S,E) ----
    const float ia = 1.0f / l_a, ib = 1.0f / l_b;
    const int b = bh / HH, h = bh % HH;
    const int rowa = q0 + warp * 16 + g, rowb = rowa + 8;
    __half* opa = AO + ((size_t)(b * SS + rowa)) * EE + h * DD;
    __half* opb = AO + ((size_t)(b * SS + rowb)) * EE + h * DD;
    #pragma unroll
    for (int nt2 = 0; nt2 < 16; nt2++) {
        int cl = nt2 * 8 + 2 * t;
        *(__half2*)(opa + cl) = __floats2half2_rn(oacc[nt2][0] * ia, oacc[nt2][1] * ia);
        *(__half2*)(opb + cl) = __floats2half2_rn(oacc[nt2][2] * ib, oacc[nt2][3] * ib);
    }
}

// ---------------------------------------------------------------------------
extern "C" void kernel_launch(void* const* d_in, const int* in_sizes, int n_in,
                              void* d_out, int out_size)
{
    const float* query  = (const float*)d_in[0];
    const float* key_in = (const float*)d_in[1];
    const float* value  = (const float*)d_in[2];
    const float* Wq = (const float*)d_in[3];
    const float* bq = (const float*)d_in[4];
    const float* Wk = (const float*)d_in[5];
    const float* bk = (const float*)d_in[6];
    const float* Wv = (const float*)d_in[7];
    const float* bv = (const float*)d_in[8];
    const float* Wo = (const float*)d_in[9];
    const float* bo = (const float*)d_in[10];
    float* out = (float*)d_out;

    __half *hq, *hk, *hv, *hWq, *hWk, *hWv, *hWo;
    __half *qbuf, *kbuf, *vtbuf, *aobuf;
    cudaGetSymbolAddress((void**)&hq,  g_hq);
    cudaGetSymbolAddress((void**)&hk,  g_hk);
    cudaGetSymbolAddress((void**)&hv,  g_hv);
    cudaGetSymbolAddress((void**)&hWq, g_hWq);
    cudaGetSymbolAddress((void**)&hWk, g_hWk);
    cudaGetSymbolAddress((void**)&hWv, g_hWv);
    cudaGetSymbolAddress((void**)&hWo, g_hWo);
    cudaGetSymbolAddress((void**)&qbuf,  g_Q);
    cudaGetSymbolAddress((void**)&kbuf,  g_K);
    cudaGetSymbolAddress((void**)&vtbuf, g_Vt);
    cudaGetSymbolAddress((void**)&aobuf, g_AO);

    cudaFuncSetAttribute(attn_h,
                         cudaFuncAttributeMaxDynamicSharedMemorySize, ATTNH_SMEM);
    cudaFuncSetAttribute(gemm_h<0>,
                         cudaFuncAttributeMaxDynamicSharedMemorySize, GEMMH_SMEM);
    cudaFuncSetAttribute(gemm_h<1>,
                         cudaFuncAttributeMaxDynamicSharedMemorySize, GEMMH_SMEM);
    cudaFuncSetAttribute(gemm_h<2>,
                         cudaFuncAttributeMaxDynamicSharedMemorySize, GEMMH_SMEM);

    // 1. fp16 conversions
    const int NX4 = MM * EE / 4;
    cvt_f2h<<<(NX4 + 255) / 256, 256>>>(query,  hq, NX4);
    cvt_f2h<<<(NX4 + 255) / 256, 256>>>(key_in, hk, NX4);
    cvt_f2h<<<(NX4 + 255) / 256, 256>>>(value,  hv, NX4);
    dim3 tgrid(EE / 32, EE / 32), tblock(32, 8);
    cvt_trans_f2h<<<tgrid, tblock>>>(Wq, hWq);
    cvt_trans_f2h<<<tgrid, tblock>>>(Wk, hWk);
    cvt_trans_f2h<<<tgrid, tblock>>>(Wv, hWv);
    cvt_trans_f2h<<<tgrid, tblock>>>(Wo, hWo);

    dim3 gblock(256);
    dim3 ggrid(EE / 128, MM / 128);  // (16, 32)

    // 2. Projections (fp16 tensor cores)
    gemm_h<1><<<ggrid, gblock, GEMMH_SMEM>>>(hq, hWq, bq, qbuf);
    gemm_h<1><<<ggrid, gblock, GEMMH_SMEM>>>(hk, hWk, bk, kbuf);
    gemm_h<2><<<ggrid, gblock, GEMMH_SMEM>>>(hv, hWv, bv, vtbuf);

    // 3. Fused fp16 tensor-core attention -> (B,S,E) fp16
    dim3 agrid(SS / 128, BB * HH);   // (16, 32)
    attn_h<<<agrid, gblock, ATTNH_SMEM>>>(qbuf, kbuf, vtbuf, aobuf);

    // 4. Output projection -> d_out fp32
    gemm_h<0><<<ggrid, gblock, GEMMH_SMEM>>>(aobuf, hWo, bo, out);
}

// round 11
// speedup vs baseline: 7.1545x; 1.0762x over previous
#include <cuda_runtime.h>
#include <cuda_fp16.h>
#include <math.h>
#include <stdint.h>

// Problem constants
#define BB 2
#define SS 2048
#define EE 2048
#define HH 16
#define DD 128
#define MM (BB*SS)

// Scratch (static __device__ — no allocation allowed)
__device__ __half g_hq[(size_t)MM*EE];     // fp16 inputs [M][K]
__device__ __half g_hk[(size_t)MM*EE];
__device__ __half g_hv[(size_t)MM*EE];
__device__ __half g_hWq[(size_t)EE*EE];    // fp16 weights transposed [N][K]
__device__ __half g_hWk[(size_t)EE*EE];
__device__ __half g_hWv[(size_t)EE*EE];
__device__ __half g_hWo[(size_t)EE*EE];
__device__ __half g_Q[(size_t)BB*HH*SS*DD];   // (B,H,S,D)
__device__ __half g_K[(size_t)BB*HH*SS*DD];   // (B,H,S,D)
__device__ __half g_Vt[(size_t)BB*HH*SS*DD];  // (B,H,D,S)  V transposed
__device__ __half g_AO[(size_t)MM*EE];        // attention out (B,S,E)

#define CP_ASYNC16(sa, gp) asm volatile("cp.async.cg.shared.global [%0], [%1], 16;\n" :: "r"(sa), "l"(gp))
#define CP_COMMIT()        asm volatile("cp.async.commit_group;\n")
#define CP_WAIT1()         asm volatile("cp.async.wait_group 1;\n")
#define CP_WAIT0()         asm volatile("cp.async.wait_group 0;\n")

#define LDSM_X4(r0, r1, r2, r3, addr) \
    asm volatile("ldmatrix.sync.aligned.m8n8.x4.shared.b16 {%0,%1,%2,%3}, [%4];\n" \
                 : "=r"(r0), "=r"(r1), "=r"(r2), "=r"(r3) : "r"(addr))

__device__ __forceinline__ void mma_f16(float c[4], const uint32_t a[4],
                                        uint32_t b0, uint32_t b1)
{
    asm volatile(
        "mma.sync.aligned.m16n8k16.row.col.f32.f16.f16.f32 "
        "{%0,%1,%2,%3}, {%4,%5,%6,%7}, {%8,%9}, {%0,%1,%2,%3};\n"
        : "+f"(c[0]), "+f"(c[1]), "+f"(c[2]), "+f"(c[3])
        : "r"(a[0]), "r"(a[1]), "r"(a[2]), "r"(a[3]), "r"(b0), "r"(b1));
}

// Lane selectors for ldmatrix.x4 address generation
__device__ __forceinline__ int lrow_a(int lane) { return lane & 15; }
__device__ __forceinline__ int lcol_a(int lane) { return (lane >> 4) * 8; }
__device__ __forceinline__ int lrow_b(int lane) { return (lane & 7) + ((lane >> 4) << 3); }
__device__ __forceinline__ int lcol_b(int lane) { return ((lane >> 3) & 1) * 8; }

// ---------------------------------------------------------------------------
// fp32 -> fp16 conversions
// ---------------------------------------------------------------------------
__global__ void cvt_f2h(const float* __restrict__ in, __half* __restrict__ out, int n4)
{
    int i = blockIdx.x * blockDim.x + threadIdx.x;
    if (i < n4) {
        float4 v = ((const float4*)in)[i];
        ((__half2*)out)[2 * i]     = __floats2half2_rn(v.x, v.y);
        ((__half2*)out)[2 * i + 1] = __floats2half2_rn(v.z, v.w);
    }
}

// W [K][N] fp32 -> Wt [N][K] fp16 (tiled transpose)
__global__ void cvt_trans_f2h(const float* __restrict__ W, __half* __restrict__ Wt)
{
    __shared__ float t[32][33];
    const int n0 = blockIdx.x * 32, k0 = blockIdx.y * 32;
    const int tx = threadIdx.x, ty = threadIdx.y;
    #pragma unroll
    for (int j = 0; j < 32; j += 8)
        t[ty + j][tx] = W[(size_t)(k0 + ty + j) * EE + n0 + tx];
    __syncthreads();
    #pragma unroll
    for (int j = 0; j < 32; j += 8)
        Wt[(size_t)(n0 + ty + j) * EE + k0 + tx] = __float2half_rn(t[tx][ty + j]);
}

// ---------------------------------------------------------------------------
// fp16 tensor-core GEMM: Y = X[M,K] * Wt[N,K]^T + bias
// MODE 0: fp32 [M,N]; MODE 1: fp16 (B,H,S,D); MODE 2: fp16 (B,H,D,S)
// Block 128x128, BK=64 (halved barrier count vs BK=32), 256 thr (8 warps 2x4),
// warp tile 64x32, mma m16n8k16, fragments via ldmatrix.x4.
// XSTRH=72: LDSM row-bank pattern r mod 8 (conflict-free).
// ---------------------------------------------------------------------------
#define BKH 64
#define XSTRH 72
#define GEMMH_SMEM (2 * 2 * 128 * XSTRH * 2)   // 73728 B

template<int MODE>
__global__ __launch_bounds__(256, 2)
void gemm_h(const __half* __restrict__ X, const __half* __restrict__ Wt,
            const float* __restrict__ bias, void* __restrict__ Yv)
{
    extern __shared__ __half smg[];
    __half* Xs = smg;                       // [2][128][XSTRH]
    __half* Ws = smg + 2 * 128 * XSTRH;     // [2][128][XSTRH]

    const int tid  = threadIdx.x;
    const int lane = tid & 31;
    const int warp = tid >> 5;
    const int g = lane >> 2, t = lane & 3;
    const int wm = (warp >> 2) * 64;
    const int wn = (warp & 3) * 32;
    const int m0 = blockIdx.y * 128, n0 = blockIdx.x * 128;

    const int ra = lrow_a(lane), ca = lcol_a(lane);
    const int rb = lrow_b(lane), cb = lcol_b(lane);

    float acc[4][4][4];
    #pragma unroll
    for (int mi = 0; mi < 4; mi++)
        #pragma unroll
        for (int ni = 0; ni < 4; ni++)
            #pragma unroll
            for (int r = 0; r < 4; r++) acc[mi][ni][r] = 0.f;

    auto issue = [&](int stage, int k0) {
        __half* xs = Xs + stage * 128 * XSTRH;
        __half* ws = Ws + stage * 128 * XSTRH;
        #pragma unroll
        for (int j = 0; j < 4; j++) {
            int c = tid + j * 256;          // 0..1023
            int r = c >> 3, ch = c & 7;     // 128 rows x 8 chunks (64 halves)
            uint32_t sa = (uint32_t)__cvta_generic_to_shared(xs + r * XSTRH + ch * 8);
            CP_ASYNC16(sa, X + (size_t)(m0 + r) * EE + k0 + ch * 8);
            uint32_t sb = (uint32_t)__cvta_generic_to_shared(ws + r * XSTRH + ch * 8);
            CP_ASYNC16(sb, Wt + (size_t)(n0 + r) * EE + k0 + ch * 8);
        }
    };

    issue(0, 0);
    CP_COMMIT();

    const int NT = EE / BKH;  // 32
    for (int it = 0; it < NT; it++) {
        if (it + 1 < NT) {
            issue((it + 1) & 1, (it + 1) * BKH);
            CP_COMMIT();
            CP_WAIT1();
        } else {
            CP_WAIT0();
        }
        __syncthreads();

        const __half* xs = Xs + (it & 1) * 128 * XSTRH;
        const __half* ws = Ws + (it & 1) * 128 * XSTRH;

        #pragma unroll
        for (int ks = 0; ks < 4; ks++) {
            uint32_t a[4][4], b[4][2];
            #pragma unroll
            for (int mi = 0; mi < 4; mi++) {
                uint32_t ad = (uint32_t)__cvta_generic_to_shared(
                    xs + (wm + mi * 16 + ra) * XSTRH + 16 * ks + ca);
                LDSM_X4(a[mi][0], a[mi][1], a[mi][2], a[mi][3], ad);
            }
            #pragma unroll
            for (int ni2 = 0; ni2 < 2; ni2++) {
                uint32_t bd = (uint32_t)__cvta_generic_to_shared(
                    ws + (wn + ni2 * 16 + rb) * XSTRH + 16 * ks + cb);
                LDSM_X4(b[2 * ni2][0], b[2 * ni2][1],
                        b[2 * ni2 + 1][0], b[2 * ni2 + 1][1], bd);
            }
            #pragma unroll
            for (int mi = 0; mi < 4; mi++)
                #pragma unroll
                for (int ni = 0; ni < 4; ni++)
                    mma_f16(acc[mi][ni], a[mi], b[ni][0], b[ni][1]);
        }
        __syncthreads();
    }

    // Epilogue
    #pragma unroll
    for (int mi = 0; mi < 4; mi++) {
        #pragma unroll
        for (int ni = 0; ni < 4; ni++) {
            int row = m0 + wm + mi * 16 + g;
            int cl  = wn + ni * 8 + 2 * t;
            int n   = n0 + cl;
            float bx = bias[n], by = bias[n + 1];
            float c00 = acc[mi][ni][0] + bx, c01 = acc[mi][ni][1] + by;
            float c10 = acc[mi][ni][2] + bx, c11 = acc[mi][ni][3] + by;
            if (MODE == 0) {
                float* Y = (float*)Yv;
                *(float2*)(Y + (size_t)row * EE + n)       = make_float2(c00, c01);
                *(float2*)(Y + (size_t)(row + 8) * EE + n) = make_float2(c10, c11);
            } else if (MODE == 1) {
                __half* Y = (__half*)Yv;
                int b0r = row >> 11, s = row & (SS - 1);
                int s2 = (row + 8) & (SS - 1);
                __half* base = Y + ((size_t)(b0r * HH + blockIdx.x) * SS + s) * DD + cl;
                *(__half2*)base = __floats2half2_rn(c00, c01);
                __half* base2 = Y + ((size_t)(b0r * HH + blockIdx.x) * SS + s2) * DD + cl;
                *(__half2*)base2 = __floats2half2_rn(c10, c11);
            } else {
                __half* Y = (__half*)Yv;
                int b0r = row >> 11, s = row & (SS - 1);
                int s2 = (row + 8) & (SS - 1);
                __half* colp = Y + ((size_t)(b0r * HH + blockIdx.x) * DD + cl) * SS;
                colp[s]  = __float2half_rn(c00);
                colp[s2] = __float2half_rn(c10);
                __half* colp2 = colp + SS;
                colp2[s]  = __float2half_rn(c01);
                colp2[s2] = __float2half_rn(c11);
            }
        }
    }
}

// ---------------------------------------------------------------------------
// fp16 tensor-core flash attention (unchanged from passing R8 kernel)
// ---------------------------------------------------------------------------
#define TKH 64
#define KSTRH 136
#define VSTRH 72
#define PSTRH 72
#define ATTNH_SMEM ((2*TKH*KSTRH + 2*DD*VSTRH + 8*16*PSTRH) * 2)

__global__ __launch_bounds__(256, 1)
void attn_h(const __half* __restrict__ Q, const __half* __restrict__ K,
            const __half* __restrict__ Vt, __half* __restrict__ AO)
{
    extern __shared__ __half smh[];
    __half* Kb = smh;                       // [2][TKH][KSTRH]
    __half* Vb = smh + 2 * TKH * KSTRH;     // [2][DD][VSTRH]
    __half* Pw = Vb + 2 * DD * VSTRH;       // [8][16][PSTRH]

    const int tid  = threadIdx.x;
    const int lane = tid & 31;
    const int warp = tid >> 5;
    const int g = lane >> 2, t = lane & 3;
    const int bh = blockIdx.y;
    const int q0 = blockIdx.x * 128;

    const int ra = lrow_a(lane), ca = lcol_a(lane);
    const int rb = lrow_b(lane), cb = lcol_b(lane);

    const __half* Qg = Q + ((size_t)bh * SS + q0) * DD;
    const __half* Kg = K + (size_t)bh * SS * DD;
    const __half* Vg = Vt + (size_t)bh * DD * SS;   // [d][s]

    // ---- stage Q (128 rows x 128 halves) into Kb, then to regs via ldmatrix ----
    #pragma unroll
    for (int j = 0; j < 8; j++) {
        int c = tid + j * 256;              // 0..2047
        int r = c >> 4, ch = c & 15;
        uint32_t sa = (uint32_t)__cvta_generic_to_shared(Kb + r * KSTRH + ch * 8);
        CP_ASYNC16(sa, Qg + (size_t)r * DD + ch * 8);
    }
    CP_COMMIT(); CP_WAIT0();
    __syncthreads();

    uint32_t qa[8][4];
    #pragma unroll
    for (int ks = 0; ks < 8; ks++) {
        uint32_t ad = (uint32_t)__cvta_generic_to_shared(
            Kb + (warp * 16 + ra) * KSTRH + 16 * ks + ca);
        LDSM_X4(qa[ks][0], qa[ks][1], qa[ks][2], qa[ks][3], ad);
    }
    __syncthreads();

    float oacc[16][4];
    #pragma unroll
    for (int n = 0; n < 16; n++)
        #pragma unroll
        for (int r = 0; r < 4; r++) oacc[n][r] = 0.f;
    float m_a = -1e30f, m_b = -1e30f, l_a = 0.f, l_b = 0.f;

    const float scale = 0.08838834764831845f;  // 1/sqrt(128)

    auto load_kv = [&](int stage, int kt) {
        __half* ks_ = Kb + stage * TKH * KSTRH;
        __half* vs_ = Vb + stage * DD * VSTRH;
        #pragma unroll
        for (int j = 0; j < 4; j++) {       // K: 64 rows x 16 chunks
            int c = tid + j * 256;
            int r = c >> 4, ch = c & 15;
            uint32_t sk = (uint32_t)__cvta_generic_to_shared(ks_ + r * KSTRH + ch * 8);
            CP_ASYNC16(sk, Kg + (size_t)(kt + r) * DD + ch * 8);
        }
        #pragma unroll
        for (int j = 0; j < 4; j++) {       // Vt: 128 d-rows x 8 chunks
            int c = tid + j * 256;
            int r = c >> 3, ch = c & 7;
            uint32_t sv = (uint32_t)__cvta_generic_to_shared(vs_ + r * VSTRH + ch * 8);
            CP_ASYNC16(sv, Vg + (size_t)r * SS + kt + ch * 8);
        }
    };

    load_kv(0, 0);
    CP_COMMIT();

    const int NTILES = SS / TKH;  // 32
    for (int it = 0; it < NTILES; it++) {
        if (it + 1 < NTILES) {
            load_kv((it + 1) & 1, (it + 1) * TKH);
            CP_COMMIT();
            CP_WAIT1();
        } else {
            CP_WAIT0();
        }
        __syncthreads();

        const __half* ks_ = Kb + (it & 1) * TKH * KSTRH;
        const __half* vs_ = Vb + (it & 1) * DD * VSTRH;

        // ---- S = Q K^T ----
        float sacc[8][4];
        #pragma unroll
        for (int n = 0; n < 8; n++)
            #pragma unroll
            for (int r = 0; r < 4; r++) sacc[n][r] = 0.f;

        #pragma unroll
        for (int ks = 0; ks < 8; ks++) {
            uint32_t b[8][2];
            #pragma unroll
            for (int ni2 = 0; ni2 < 4; ni2++) {
                uint32_t bd = (uint32_t)__cvta_generic_to_shared(
                    ks_ + (ni2 * 16 + rb) * KSTRH + 16 * ks + cb);
                LDSM_X4(b[2 * ni2][0], b[2 * ni2][1],
                        b[2 * ni2 + 1][0], b[2 * ni2 + 1][1], bd);
            }
            #pragma unroll
            for (int nt = 0; nt < 8; nt++)
                mma_f16(sacc[nt], qa[ks], b[nt][0], b[nt][1]);
        }

        // ---- online softmax ----
        float mxa = -1e30f, mxb = -1e30f;
        #pragma unroll
        for (int nt = 0; nt < 8; nt++) {
            sacc[nt][0] *= scale; sacc[nt][1] *= scale;
            sacc[nt][2] *= scale; sacc[nt][3] *= scale;
            mxa = fmaxf(mxa, fmaxf(sacc[nt][0], sacc[nt][1]));
            mxb = fmaxf(mxb, fmaxf(sacc[nt][2], sacc[nt][3]));
        }
        mxa = fmaxf(mxa, __shfl_xor_sync(0xffffffffu, mxa, 1));
        mxa = fmaxf(mxa, __shfl_xor_sync(0xffffffffu, mxa, 2));
        mxb = fmaxf(mxb, __shfl_xor_sync(0xffffffffu, mxb, 1));
        mxb = fmaxf(mxb, __shfl_xor_sync(0xffffffffu, mxb, 2));

        float mna = fmaxf(m_a, mxa), mnb = fmaxf(m_b, mxb);
        float ca2 = __expf(m_a - mna), cb2 = __expf(m_b - mnb);
        m_a = mna; m_b = mnb;

        float ra2 = 0.f, rb2 = 0.f;
        __half* pw = Pw + warp * 16 * PSTRH;
        #pragma unroll
        for (int nt = 0; nt < 8; nt++) {
            __half h0 = __float2half_rn(__expf(sacc[nt][0] - mna));
            __half h1 = __float2half_rn(__expf(sacc[nt][1] - mna));
            __half h2 = __float2half_rn(__expf(sacc[nt][2] - mnb));
            __half h3 = __float2half_rn(__expf(sacc[nt][3] - mnb));
            ra2 += __half2float(h0) + __half2float(h1);
            rb2 += __half2float(h2) + __half2float(h3);
            __half2 pa01; pa01.x = h0; pa01.y = h1;
            __half2 pa23; pa23.x = h2; pa23.y = h3;
            *(__half2*)&pw[g * PSTRH + nt * 8 + 2 * t]       = pa01;
            *(__half2*)&pw[(g + 8) * PSTRH + nt * 8 + 2 * t] = pa23;
        }
        ra2 += __shfl_xor_sync(0xffffffffu, ra2, 1);
        ra2 += __shfl_xor_sync(0xffffffffu, ra2, 2);
        rb2 += __shfl_xor_sync(0xffffffffu, rb2, 1);
        rb2 += __shfl_xor_sync(0xffffffffu, rb2, 2);
        l_a = l_a * ca2 + ra2;
        l_b = l_b * cb2 + rb2;

        #pragma unroll
        for (int n = 0; n < 16; n++) {
            oacc[n][0] *= ca2; oacc[n][1] *= ca2;
            oacc[n][2] *= cb2; oacc[n][3] *= cb2;
        }
        __syncwarp();

        // ---- O += P V ----
        #pragma unroll
        for (int k2 = 0; k2 < 4; k2++) {
            uint32_t pa[4];
            uint32_t pd = (uint32_t)__cvta_generic_to_shared(
                pw + ra * PSTRH + 16 * k2 + ca);
            LDSM_X4(pa[0], pa[1], pa[2], pa[3], pd);
            #pragma unroll
            for (int ni2 = 0; ni2 < 8; ni2++) {
                uint32_t b[4];
                uint32_t bd = (uint32_t)__cvta_generic_to_shared(
                    vs_ + (ni2 * 16 + rb) * VSTRH + 16 * k2 + cb);
                LDSM_X4(b[0], b[1], b[2], b[3], bd);
                mma_f16(oacc[2 * ni2],     pa, b[0], b[1]);
                mma_f16(oacc[2 * ni2 + 1], pa, b[2], b[3]);
            }
        }
        __syncthreads();
    }

    // ---- epilogue: normalize + store AO fp16 (B,S,E) ----
    const float ia = 1.0f / l_a, ib = 1.0f / l_b;
    const int b = bh / HH, h = bh % HH;
    const int rowa = q0 + warp * 16 + g, rowb = rowa + 8;
    __half* opa = AO + ((size_t)(b * SS + rowa)) * EE + h * DD;
    __half* opb = AO + ((size_t)(b * SS + rowb)) * EE + h * DD;
    #pragma unroll
    for (int nt2 = 0; nt2 < 16; nt2++) {
        int cl = nt2 * 8 + 2 * t;
        *(__half2*)(opa + cl) = __floats2half2_rn(oacc[nt2][0] * ia, oacc[nt2][1] * ia);
        *(__half2*)(opb + cl) = __floats2half2_rn(oacc[nt2][2] * ib, oacc[nt2][3] * ib);
    }
}

// ---------------------------------------------------------------------------
extern "C" void kernel_launch(void* const* d_in, const int* in_sizes, int n_in,
                              void* d_out, int out_size)
{
    const float* query  = (const float*)d_in[0];
    const float* key_in = (const float*)d_in[1];
    const float* value  = (const float*)d_in[2];
    const float* Wq = (const float*)d_in[3];
    const float* bq = (const float*)d_in[4];
    const float* Wk = (const float*)d_in[5];
    const float* bk = (const float*)d_in[6];
    const float* Wv = (const float*)d_in[7];
    const float* bv = (const float*)d_in[8];
    const float* Wo = (const float*)d_in[9];
    const float* bo = (const float*)d_in[10];
    float* out = (float*)d_out;

    __half *hq, *hk, *hv, *hWq, *hWk, *hWv, *hWo;
    __half *qbuf, *kbuf, *vtbuf, *aobuf;
    cudaGetSymbolAddress((void**)&hq,  g_hq);
    cudaGetSymbolAddress((void**)&hk,  g_hk);
    cudaGetSymbolAddress((void**)&hv,  g_hv);
    cudaGetSymbolAddress((void**)&hWq, g_hWq);
    cudaGetSymbolAddress((void**)&hWk, g_hWk);
    cudaGetSymbolAddress((void**)&hWv, g_hWv);
    cudaGetSymbolAddress((void**)&hWo, g_hWo);
    cudaGetSymbolAddress((void**)&qbuf,  g_Q);
    cudaGetSymbolAddress((void**)&kbuf,  g_K);
    cudaGetSymbolAddress((void**)&vtbuf, g_Vt);
    cudaGetSymbolAddress((void**)&aobuf, g_AO);

    cudaFuncSetAttribute(attn_h,
                         cudaFuncAttributeMaxDynamicSharedMemorySize, ATTNH_SMEM);
    cudaFuncSetAttribute(gemm_h<0>,
                         cudaFuncAttributeMaxDynamicSharedMemorySize, GEMMH_SMEM);
    cudaFuncSetAttribute(gemm_h<1>,
                         cudaFuncAttributeMaxDynamicSharedMemorySize, GEMMH_SMEM);
    cudaFuncSetAttribute(gemm_h<2>,
                         cudaFuncAttributeMaxDynamicSharedMemorySize, GEMMH_SMEM);

    // 1. fp16 conversions
    const int NX4 = MM * EE / 4;
    cvt_f2h<<<(NX4 + 255) / 256, 256>>>(query,  hq, NX4);
    cvt_f2h<<<(NX4 + 255) / 256, 256>>>(key_in, hk, NX4);
    cvt_f2h<<<(NX4 + 255) / 256, 256>>>(value,  hv, NX4);
    dim3 tgrid(EE / 32, EE / 32), tblock(32, 8);
    cvt_trans_f2h<<<tgrid, tblock>>>(Wq, hWq);
    cvt_trans_f2h<<<tgrid, tblock>>>(Wk, hWk);
    cvt_trans_f2h<<<tgrid, tblock>>>(Wv, hWv);
    cvt_trans_f2h<<<tgrid, tblock>>>(Wo, hWo);

    dim3 gblock(256);
    dim3 ggrid(EE / 128, MM / 128);  // (16, 32)

    // 2. Projections (fp16 tensor cores)
    gemm_h<1><<<ggrid, gblock, GEMMH_SMEM>>>(hq, hWq, bq, qbuf);
    gemm_h<1><<<ggrid, gblock, GEMMH_SMEM>>>(hk, hWk, bk, kbuf);
    gemm_h<2><<<ggrid, gblock, GEMMH_SMEM>>>(hv, hWv, bv, vtbuf);

    // 3. Fused fp16 tensor-core attention -> (B,S,E) fp16
    dim3 agrid(SS / 128, BB * HH);   // (16, 32)
    attn_h<<<agrid, gblock, ATTNH_SMEM>>>(qbuf, kbuf, vtbuf, aobuf);

    // 4. Output projection -> d_out fp32
    gemm_h<0><<<ggrid, gblock, GEMMH_SMEM>>>(aobuf, hWo, bo, out);
}

// round 14
// speedup vs baseline: 7.4225x; 1.0375x over previous
#include <cuda_runtime.h>
#include <cuda_fp16.h>
#include <math.h>
#include <stdint.h>

// Problem constants
#define BB 2
#define SS 2048
#define EE 2048
#define HH 16
#define DD 128
#define MM (BB*SS)

// Scratch (static __device__ — no allocation allowed)
__device__ __half g_hq[(size_t)MM*EE];     // fp16 inputs [M][K]
__device__ __half g_hk[(size_t)MM*EE];
__device__ __half g_hv[(size_t)MM*EE];
__device__ __half g_hWq[(size_t)EE*EE];    // fp16 weights transposed [N][K]
__device__ __half g_hWk[(size_t)EE*EE];
__device__ __half g_hWv[(size_t)EE*EE];
__device__ __half g_hWo[(size_t)EE*EE];
__device__ __half g_Q[(size_t)BB*HH*SS*DD];   // (B,H,S,D)
__device__ __half g_K[(size_t)BB*HH*SS*DD];   // (B,H,S,D)
__device__ __half g_Vt[(size_t)BB*HH*SS*DD];  // (B,H,D,S)  V transposed
__device__ __half g_AO[(size_t)MM*EE];        // attention out (B,S,E)

#define CP_ASYNC16(sa, gp) asm volatile("cp.async.cg.shared.global [%0], [%1], 16;\n" :: "r"(sa), "l"(gp))
#define CP_COMMIT()        asm volatile("cp.async.commit_group;\n")
#define CP_WAIT1()         asm volatile("cp.async.wait_group 1;\n")
#define CP_WAIT0()         asm volatile("cp.async.wait_group 0;\n")

#define LDSM_X4(r0, r1, r2, r3, addr) \
    asm volatile("ldmatrix.sync.aligned.m8n8.x4.shared.b16 {%0,%1,%2,%3}, [%4];\n" \
                 : "=r"(r0), "=r"(r1), "=r"(r2), "=r"(r3) : "r"(addr))

__device__ __forceinline__ void mma_f16(float c[4], const uint32_t a[4],
                                        uint32_t b0, uint32_t b1)
{
    asm volatile(
        "mma.sync.aligned.m16n8k16.row.col.f32.f16.f16.f32 "
        "{%0,%1,%2,%3}, {%4,%5,%6,%7}, {%8,%9}, {%0,%1,%2,%3};\n"
        : "+f"(c[0]), "+f"(c[1]), "+f"(c[2]), "+f"(c[3])
        : "r"(a[0]), "r"(a[1]), "r"(a[2]), "r"(a[3]), "r"(b0), "r"(b1));
}

// Lane selectors for ldmatrix.x4 address generation
__device__ __forceinline__ int lrow_a(int lane) { return lane & 15; }
__device__ __forceinline__ int lcol_a(int lane) { return (lane >> 4) * 8; }
__device__ __forceinline__ int lrow_b(int lane) { return (lane & 7) + ((lane >> 4) << 3); }
__device__ __forceinline__ int lcol_b(int lane) { return ((lane >> 3) & 1) * 8; }

// ---------------------------------------------------------------------------
// fp32 -> fp16 conversions (merged launches)
// ---------------------------------------------------------------------------
__global__ void cvt_f2h_3(const float* __restrict__ i0, const float* __restrict__ i1,
                          const float* __restrict__ i2,
                          __half* __restrict__ o0, __half* __restrict__ o1,
                          __half* __restrict__ o2, int n4)
{
    const int z = blockIdx.z;
    const float* in = (z == 0) ? i0 : (z == 1) ? i1 : i2;
    __half* out     = (z == 0) ? o0 : (z == 1) ? o1 : o2;
    int i = blockIdx.x * blockDim.x + threadIdx.x;
    if (i < n4) {
        float4 v = ((const float4*)in)[i];
        ((__half2*)out)[2 * i]     = __floats2half2_rn(v.x, v.y);
        ((__half2*)out)[2 * i + 1] = __floats2half2_rn(v.z, v.w);
    }
}

// W [K][N] fp32 -> Wt [N][K] fp16 (tiled transpose), 4 weights in one launch
__global__ void cvt_trans_f2h_4(
    const float* __restrict__ w0, const float* __restrict__ w1,
    const float* __restrict__ w2, const float* __restrict__ w3,
    __half* __restrict__ t0, __half* __restrict__ t1,
    __half* __restrict__ t2, __half* __restrict__ t3)
{
    const int z = blockIdx.z;
    const float* W = (z == 0) ? w0 : (z == 1) ? w1 : (z == 2) ? w2 : w3;
    __half* Wt     = (z == 0) ? t0 : (z == 1) ? t1 : (z == 2) ? t2 : t3;

    __shared__ float t[32][33];
    const int n0 = blockIdx.x * 32, k0 = blockIdx.y * 32;
    const int tx = threadIdx.x, ty = threadIdx.y;
    #pragma unroll
    for (int j = 0; j < 32; j += 8)
        t[ty + j][tx] = W[(size_t)(k0 + ty + j) * EE + n0 + tx];
    __syncthreads();
    #pragma unroll
    for (int j = 0; j < 32; j += 8)
        Wt[(size_t)(n0 + ty + j) * EE + k0 + tx] = __float2half_rn(t[tx][ty + j]);
}

// ---------------------------------------------------------------------------
// fp16 tensor-core GEMM: Y = X[M,K] * Wt[N,K]^T + bias
// IS_QKV=1: blockIdx.z selects (X,Wt,bias,Y); z<2 -> (B,H,S,D) fp16,
//           z==2 -> (B,H,D,S) fp16 (V transposed).
// IS_QKV=0: single GEMM, fp32 [M,N] output (Wo projection).
// Block 128x128, BK=64, 3-stage cp.async ring, 256 thr (8 warps 2x4),
// warp tile 64x32, mma m16n8k16, fragments via ldmatrix.x4 (XSTRH=72).
// ---------------------------------------------------------------------------
#define BKH 64
#define XSTRH 72
#define GEMMH3_SMEM (3 * 2 * 128 * XSTRH * 2)   // 110592 B (3 stages, A+B)

template<int IS_QKV>
__global__ __launch_bounds__(256, 2)
void gemm_h3(const __half* __restrict__ X0, const __half* __restrict__ X1,
             const __half* __restrict__ X2,
             const __half* __restrict__ W0, const __half* __restrict__ W1,
             const __half* __restrict__ W2,
             const float* __restrict__ B0, const float* __restrict__ B1,
             const float* __restrict__ B2,
             void* __restrict__ Y0, void* __restrict__ Y1, void* __restrict__ Y2)
{
    const __half* X;
    const __half* Wt;
    const float* bias;
    void* Yv;
    int mode;
    if (IS_QKV) {
        const int z = blockIdx.z;
        X    = (z == 0) ? X0 : (z == 1) ? X1 : X2;
        Wt   = (z == 0) ? W0 : (z == 1) ? W1 : W2;
        bias = (z == 0) ? B0 : (z == 1) ? B1 : B2;
        Yv   = (z == 0) ? Y0 : (z == 1) ? Y1 : Y2;
        mode = (z == 2) ? 2 : 1;
    } else {
        X = X0; Wt = W0; bias = B0; Yv = Y0; mode = 0;
    }

    extern __shared__ __half smg[];
    // stage s: A at smg + s*2*128*XSTRH, B at +128*XSTRH
    const int tid  = threadIdx.x;
    const int lane = tid & 31;
    const int warp = tid >> 5;
    const int g = lane >> 2, t = lane & 3;
    const int wm = (warp >> 2) * 64;
    const int wn = (warp & 3) * 32;
    const int m0 = blockIdx.y * 128, n0 = blockIdx.x * 128;

    const int ra = lrow_a(lane), ca = lcol_a(lane);
    const int rb = lrow_b(lane), cb = lcol_b(lane);

    float acc[4][4][4];
    #pragma unroll
    for (int mi = 0; mi < 4; mi++)
        #pragma unroll
        for (int ni = 0; ni < 4; ni++)
            #pragma unroll
            for (int r = 0; r < 4; r++) acc[mi][ni][r] = 0.f;

    auto issue = [&](int stage, int k0) {
        __half* xs = smg + stage * 2 * 128 * XSTRH;
        __half* ws = xs + 128 * XSTRH;
        #pragma unroll
        for (int j = 0; j < 4; j++) {
            int c = tid + j * 256;          // 0..1023
            int r = c >> 3, ch = c & 7;     // 128 rows x 8 chunks (64 halves)
            uint32_t sa = (uint32_t)__cvta_generic_to_shared(xs + r * XSTRH + ch * 8);
            CP_ASYNC16(sa, X + (size_t)(m0 + r) * EE + k0 + ch * 8);
            uint32_t sb = (uint32_t)__cvta_generic_to_shared(ws + r * XSTRH + ch * 8);
            CP_ASYNC16(sb, Wt + (size_t)(n0 + r) * EE + k0 + ch * 8);
        }
    };

    const int NT = EE / BKH;  // 32
    issue(0, 0);       CP_COMMIT();
    issue(1, BKH);     CP_COMMIT();

    for (int it = 0; it < NT; it++) {
        const int s = it % 3;
        if (it + 1 < NT) CP_WAIT1();   // group 'it' complete (≤1 pending)
        else             CP_WAIT0();
        __syncthreads();

        const __half* xs = smg + s * 2 * 128 * XSTRH;
        const __half* ws = xs + 128 * XSTRH;

        #pragma unroll
        for (int ks = 0; ks < 4; ks++) {
            uint32_t a[4][4], b[4][2];
            #pragma unroll
            for (int mi = 0; mi < 4; mi++) {
                uint32_t ad = (uint32_t)__cvta_generic_to_shared(
                    xs + (wm + mi * 16 + ra) * XSTRH + 16 * ks + ca);
                LDSM_X4(a[mi][0], a[mi][1], a[mi][2], a[mi][3], ad);
            }
            #pragma unroll
            for (int ni2 = 0; ni2 < 2; ni2++) {
                uint32_t bd = (uint32_t)__cvta_generic_to_shared(
                    ws + (wn + ni2 * 16 + rb) * XSTRH + 16 * ks + cb);
                LDSM_X4(b[2 * ni2][0], b[2 * ni2][1],
                        b[2 * ni2 + 1][0], b[2 * ni2 + 1][1], bd);
            }
            #pragma unroll
            for (int mi = 0; mi < 4; mi++)
                #pragma unroll
                for (int ni = 0; ni < 4; ni++)
                    mma_f16(acc[mi][ni], a[mi], b[ni][0], b[ni][1]);
        }
        __syncthreads();   // all warps done reading stage s

        if (it + 2 < NT) {
            issue((it + 2) % 3, (it + 2) * BKH);
            CP_COMMIT();
        }
    }

    // Epilogue
    #pragma unroll
    for (int mi = 0; mi < 4; mi++) {
        #pragma unroll
        for (int ni = 0; ni < 4; ni++) {
            int row = m0 + wm + mi * 16 + g;
            int cl  = wn + ni * 8 + 2 * t;
            int n   = n0 + cl;
            float bx = bias[n], by = bias[n + 1];
            float c00 = acc[mi][ni][0] + bx, c01 = acc[mi][ni][1] + by;
            float c10 = acc[mi][ni][2] + bx, c11 = acc[mi][ni][3] + by;
            if (mode == 0) {
                float* Y = (float*)Yv;
                *(float2*)(Y + (size_t)row * EE + n)       = make_float2(c00, c01);
                *(float2*)(Y + (size_t)(row + 8) * EE + n) = make_float2(c10, c11);
            } else if (mode == 1) {
                __half* Y = (__half*)Yv;
                int b0r = row >> 11, s = row & (SS - 1);
                int s2 = (row + 8) & (SS - 1);
                __half* base = Y + ((size_t)(b0r * HH + blockIdx.x) * SS + s) * DD + cl;
                *(__half2*)base = __floats2half2_rn(c00, c01);
                __half* base2 = Y + ((size_t)(b0r * HH + blockIdx.x) * SS + s2) * DD + cl;
                *(__half2*)base2 = __floats2half2_rn(c10, c11);
            } else {
                __half* Y = (__half*)Yv;
                int b0r = row >> 11, s = row & (SS - 1);
                int s2 = (row + 8) & (SS - 1);
                __half* colp = Y + ((size_t)(b0r * HH + blockIdx.x) * DD + cl) * SS;
                colp[s]  = __float2half_rn(c00);
                colp[s2] = __float2half_rn(c10);
                __half* colp2 = colp + SS;
                colp2[s]  = __float2half_rn(c01);
                colp2[s2] = __float2half_rn(c11);
            }
        }
    }
}

// ---------------------------------------------------------------------------
// fp16 tensor-core flash attention (unchanged from passing R10 kernel)
// ---------------------------------------------------------------------------
#define TKH 64
#define KSTRH 136
#define VSTRH 72
#define PSTRH 72
#define ATTNH_SMEM ((2*TKH*KSTRH + 2*DD*VSTRH + 8*16*PSTRH) * 2)

__global__ __launch_bounds__(256, 1)
void attn_h(const __half* __restrict__ Q, const __half* __restrict__ K,
            const __half* __restrict__ Vt, __half* __restrict__ AO)
{
    extern __shared__ __half smh[];
    __half* Kb = smh;                       // [2][TKH][KSTRH]
    __half* Vb = smh + 2 * TKH * KSTRH;     // [2][DD][VSTRH]
    __half* Pw = Vb + 2 * DD * VSTRH;       // [8][16][PSTRH]

    const int tid  = threadIdx.x;
    const int lane = tid & 31;
    const int warp = tid >> 5;
    const int g = lane >> 2, t = lane & 3;
    const int bh = blockIdx.y;
    const int q0 = blockIdx.x * 128;

    const int ra = lrow_a(lane), ca = lcol_a(lane);
    const int rb = lrow_b(lane), cb = lcol_b(lane);

    const __half* Qg = Q + ((size_t)bh * SS + q0) * DD;
    const __half* Kg = K + (size_t)bh * SS * DD;
    const __half* Vg = Vt + (size_t)bh * DD * SS;   // [d][s]

    #pragma unroll
    for (int j = 0; j < 8; j++) {
        int c = tid + j * 256;              // 0..2047
        int r = c >> 4, ch = c & 15;
        uint32_t sa = (uint32_t)__cvta_generic_to_shared(Kb + r * KSTRH + ch * 8);
        CP_ASYNC16(sa, Qg + (size_t)r * DD + ch * 8);
    }
    CP_COMMIT(); CP_WAIT0();
    __syncthreads();

    uint32_t qa[8][4];
    #pragma unroll
    for (int ks = 0; ks < 8; ks++) {
        uint32_t ad = (uint32_t)__cvta_generic_to_shared(
            Kb + (warp * 16 + ra) * KSTRH + 16 * ks + ca);
        LDSM_X4(qa[ks][0], qa[ks][1], qa[ks][2], qa[ks][3], ad);
    }
    __syncthreads();

    float oacc[16][4];
    #pragma unroll
    for (int n = 0; n < 16; n++)
        #pragma unroll
        for (int r = 0; r < 4; r++) oacc[n][r] = 0.f;
    float m_a = -1e30f, m_b = -1e30f, l_a = 0.f, l_b = 0.f;

    const float scale = 0.08838834764831845f;  // 1/sqrt(128)

    auto load_kv = [&](int stage, int kt) {
        __half* ks_ = Kb + stage * TKH * KSTRH;
        __half* vs_ = Vb + stage * DD * VSTRH;
        #pragma unroll
        for (int j = 0; j < 4; j++) {       // K: 64 rows x 16 chunks
            int c = tid + j * 256;
            int r = c >> 4, ch = c & 15;
            uint32_t sk = (uint32_t)__cvta_generic_to_shared(ks_ + r * KSTRH + ch * 8);
            CP_ASYNC16(sk, Kg + (size_t)(kt + r) * DD + ch * 8);
        }
        #pragma unroll
        for (int j = 0; j < 4; j++) {       // Vt: 128 d-rows x 8 chunks
            int c = tid + j * 256;
            int r = c >> 3, ch = c & 7;
            uint32_t sv = (uint32_t)__cvta_generic_to_shared(vs_ + r * VSTRH + ch * 8);
            CP_ASYNC16(sv, Vg + (size_t)r * SS + kt + ch * 8);
        }
    };

    load_kv(0, 0);
    CP_COMMIT();

    const int NTILES = SS / TKH;  // 32
    for (int it = 0; it < NTILES; it++) {
        if (it + 1 < NTILES) {
            load_kv((it + 1) & 1, (it + 1) * TKH);
            CP_COMMIT();
            CP_WAIT1();
        } else {
            CP_WAIT0();
        }
        __syncthreads();

        const __half* ks_ = Kb + (it & 1) * TKH * KSTRH;
        const __half* vs_ = Vb + (it & 1) * DD * VSTRH;

        float sacc[8][4];
        #pragma unroll
        for (int n = 0; n < 8; n++)
            #pragma unroll
            for (int r = 0; r < 4; r++) sacc[n][r] = 0.f;

        #pragma unroll
        for (int ks = 0; ks < 8; ks++) {
            uint32_t b[8][2];
            #pragma unroll
            for (int ni2 = 0; ni2 < 4; ni2++) {
                uint32_t bd = (uint32_t)__cvta_generic_to_shared(
                    ks_ + (ni2 * 16 + rb) * KSTRH + 16 * ks + cb);
                LDSM_X4(b[2 * ni2][0], b[2 * ni2][1],
                        b[2 * ni2 + 1][0], b[2 * ni2 + 1][1], bd);
            }
            #pragma unroll
            for (int nt = 0; nt < 8; nt++)
                mma_f16(sacc[nt], qa[ks], b[nt][0], b[nt][1]);
        }

        float mxa = -1e30f, mxb = -1e30f;
        #pragma unroll
        for (int nt = 0; nt < 8; nt++) {
            sacc[nt][0] *= scale; sacc[nt][1] *= scale;
            sacc[nt][2] *= scale; sacc[nt][3] *= scale;
            mxa = fmaxf(mxa, fmaxf(sacc[nt][0], sacc[nt][1]));
            mxb = fmaxf(mxb, fmaxf(sacc[nt][2], sacc[nt][3]));
        }
        mxa = fmaxf(mxa, __shfl_xor_sync(0xffffffffu, mxa, 1));
        mxa = fmaxf(mxa, __shfl_xor_sync(0xffffffffu, mxa, 2));
        mxb = fmaxf(mxb, __shfl_xor_sync(0xffffffffu, mxb, 1));
        mxb = fmaxf(mxb, __shfl_xor_sync(0xffffffffu, mxb, 2));

        float mna = fmaxf(m_a, mxa), mnb = fmaxf(m_b, mxb);
        float ca2 = __expf(m_a - mna), cb2 = __expf(m_b - mnb);
        m_a = mna; m_b = mnb;

        float ra2 = 0.f, rb2 = 0.f;
        __half* pw = Pw + warp * 16 * PSTRH;
        #pragma unroll
        for (int nt = 0; nt < 8; nt++) {
            __half h0 = __float2half_rn(__expf(sacc[nt][0] - mna));
            __half h1 = __float2half_rn(__expf(sacc[nt][1] - mna));
            __half h2 = __float2half_rn(__expf(sacc[nt][2] - mnb));
            __half h3 = __float2half_rn(__expf(sacc[nt][3] - mnb));
            ra2 += __half2float(h0) + __half2float(h1);
            rb2 += __half2float(h2) + __half2float(h3);
            __half2 pa01; pa01.x = h0; pa01.y = h1;
            __half2 pa23; pa23.x = h2; pa23.y = h3;
            *(__half2*)&pw[g * PSTRH + nt * 8 + 2 * t]       = pa01;
            *(__half2*)&pw[(g + 8) * PSTRH + nt * 8 + 2 * t] = pa23;
        }
        ra2 += __shfl_xor_sync(0xffffffffu, ra2, 1);
        ra2 += __shfl_xor_sync(0xffffffffu, ra2, 2);
        rb2 += __shfl_xor_sync(0xffffffffu, rb2, 1);
        rb2 += __shfl_xor_sync(0xffffffffu, rb2, 2);
        l_a = l_a * ca2 + ra2;
        l_b = l_b * cb2 + rb2;

        #pragma unroll
        for (int n = 0; n < 16; n++) {
            oacc[n][0] *= ca2; oacc[n][1] *= ca2;
            oacc[n][2] *= cb2; oacc[n][3] *= cb2;
        }
        __syncwarp();

        #pragma unroll
        for (int k2 = 0; k2 < 4; k2++) {
            uint32_t pa[4];
            uint32_t pd = (uint32_t)__cvta_generic_to_shared(
                pw + ra * PSTRH + 16 * k2 + ca);
            LDSM_X4(pa[0], pa[1], pa[2], pa[3], pd);
            #pragma unroll
            for (int ni2 = 0; ni2 < 8; ni2++) {
                uint32_t b[4];
                uint32_t bd = (uint32_t)__cvta_generic_to_shared(
                    vs_ + (ni2 * 16 + rb) * VSTRH + 16 * k2 + cb);
                LDSM_X4(b[0], b[1], b[2], b[3], bd);
                mma_f16(oacc[2 * ni2],     pa, b[0], b[1]);
                mma_f16(oacc[2 * ni2 + 1], pa, b[2], b[3]);
            }
        }
        __syncthreads();
    }

    const float ia = 1.0f / l_a, ib = 1.0f / l_b;
    const int b = bh / HH, h = bh % HH;
    const int rowa = q0 + warp * 16 + g, rowb = rowa + 8;
    __half* opa = AO + ((size_t)(b * SS + rowa)) * EE + h * DD;
    __half* opb = AO + ((size_t)(b * SS + rowb)) * EE + h * DD;
    #pragma unroll
    for (int nt2 = 0; nt2 < 16; nt2++) {
        int cl = nt2 * 8 + 2 * t;
        *(__half2*)(opa + cl) = __floats2half2_rn(oacc[nt2][0] * ia, oacc[nt2][1] * ia);
        *(__half2*)(opb + cl) = __floats2half2_rn(oacc[nt2][2] * ib, oacc[nt2][3] * ib);
    }
}

// ---------------------------------------------------------------------------
extern "C" void kernel_launch(void* const* d_in, const int* in_sizes, int n_in,
                              void* d_out, int out_size)
{
    const float* query  = (const float*)d_in[0];
    const float* key_in = (const float*)d_in[1];
    const float* value  = (const float*)d_in[2];
    const float* Wq = (const float*)d_in[3];
    const float* bq = (const float*)d_in[4];
    const float* Wk = (const float*)d_in[5];
    const float* bk = (const float*)d_in[6];
    const float* Wv = (const float*)d_in[7];
    const float* bv = (const float*)d_in[8];
    const float* Wo = (const float*)d_in[9];
    const float* bo = (const float*)d_in[10];
    float* out = (float*)d_out;

    __half *hq, *hk, *hv, *hWq, *hWk, *hWv, *hWo;
    __half *qbuf, *kbuf, *vtbuf, *aobuf;
    cudaGetSymbolAddress((void**)&hq,  g_hq);
    cudaGetSymbolAddress((void**)&hk,  g_hk);
    cudaGetSymbolAddress((void**)&hv,  g_hv);
    cudaGetSymbolAddress((void**)&hWq, g_hWq);
    cudaGetSymbolAddress((void**)&hWk, g_hWk);
    cudaGetSymbolAddress((void**)&hWv, g_hWv);
    cudaGetSymbolAddress((void**)&hWo, g_hWo);
    cudaGetSymbolAddress((void**)&qbuf,  g_Q);
    cudaGetSymbolAddress((void**)&kbuf,  g_K);
    cudaGetSymbolAddress((void**)&vtbuf, g_Vt);
    cudaGetSymbolAddress((void**)&aobuf, g_AO);

    cudaFuncSetAttribute(attn_h,
                         cudaFuncAttributeMaxDynamicSharedMemorySize, ATTNH_SMEM);
    cudaFuncSetAttribute(gemm_h3<0>,
                         cudaFuncAttributeMaxDynamicSharedMemorySize, GEMMH3_SMEM);
    cudaFuncSetAttribute(gemm_h3<1>,
                         cudaFuncAttributeMaxDynamicSharedMemorySize, GEMMH3_SMEM);

    // 1. fp16 conversions (2 launches)
    const int NX4 = MM * EE / 4;
    dim3 cgrid((NX4 + 255) / 256, 1, 3);
    cvt_f2h_3<<<cgrid, 256>>>(query, key_in, value, hq, hk, hv, NX4);
    dim3 tgrid(EE / 32, EE / 32, 4), tblock(32, 8);
    cvt_trans_f2h_4<<<tgrid, tblock>>>(Wq, Wk, Wv, Wo, hWq, hWk, hWv, hWo);

    // 2. Q/K/V projections in ONE launch (z selects GEMM)
    dim3 qkvgrid(EE / 128, MM / 128, 3);   // (16, 32, 3)
    gemm_h3<1><<<qkvgrid, 256, GEMMH3_SMEM>>>(
        hq, hk, hv, hWq, hWk, hWv, bq, bk, bv, qbuf, kbuf, vtbuf);

    // 3. Fused fp16 tensor-core attention -> (B,S,E) fp16
    dim3 agrid(SS / 128, BB * HH);   // (16, 32)
    attn_h<<<agrid, 256, ATTNH_SMEM>>>(qbuf, kbuf, vtbuf, aobuf);

    // 4. Output projection -> d_out fp32
    dim3 ogrid(EE / 128, MM / 128, 1);
    gemm_h3<0><<<ogrid, 256, GEMMH3_SMEM>>>(
        aobuf, nullptr, nullptr, hWo, nullptr, nullptr,
        bo, nullptr, nullptr, out, nullptr, nullptr);
}

// round 15
// speedup vs baseline: 8.0142x; 1.0797x over previous
#include <cuda_runtime.h>
#include <cuda_fp16.h>
#include <math.h>
#include <stdint.h>

// Problem constants
#define BB 2
#define SS 2048
#define EE 2048
#define HH 16
#define DD 128
#define MM (BB*SS)

// Scratch (static __device__ — no allocation allowed)
__device__ __half g_hq[(size_t)MM*EE];     // fp16 inputs [M][K]
__device__ __half g_hk[(size_t)MM*EE];
__device__ __half g_hv[(size_t)MM*EE];
__device__ __half g_hWq[(size_t)EE*EE];    // fp16 weights transposed [N][K]
__device__ __half g_hWk[(size_t)EE*EE];
__device__ __half g_hWv[(size_t)EE*EE];
__device__ __half g_hWo[(size_t)EE*EE];
__device__ __half g_Q[(size_t)BB*HH*SS*DD];   // (B,H,S,D)
__device__ __half g_K[(size_t)BB*HH*SS*DD];   // (B,H,S,D)
__device__ __half g_Vt[(size_t)BB*HH*SS*DD];  // (B,H,D,S)  V transposed
__device__ __half g_AO[(size_t)MM*EE];        // attention out (B,S,E)

#define CP_ASYNC16(sa, gp) asm volatile("cp.async.cg.shared.global [%0], [%1], 16;\n" :: "r"(sa), "l"(gp))
#define CP_COMMIT()        asm volatile("cp.async.commit_group;\n")
#define CP_WAIT1()         asm volatile("cp.async.wait_group 1;\n")
#define CP_WAIT0()         asm volatile("cp.async.wait_group 0;\n")

#define LDSM_X4(r0, r1, r2, r3, addr) \
    asm volatile("ldmatrix.sync.aligned.m8n8.x4.shared.b16 {%0,%1,%2,%3}, [%4];\n" \
                 : "=r"(r0), "=r"(r1), "=r"(r2), "=r"(r3) : "r"(addr))

__device__ __forceinline__ void mma_f16(float c[4], const uint32_t a[4],
                                        uint32_t b0, uint32_t b1)
{
    asm volatile(
        "mma.sync.aligned.m16n8k16.row.col.f32.f16.f16.f32 "
        "{%0,%1,%2,%3}, {%4,%5,%6,%7}, {%8,%9}, {%0,%1,%2,%3};\n"
        : "+f"(c[0]), "+f"(c[1]), "+f"(c[2]), "+f"(c[3])
        : "r"(a[0]), "r"(a[1]), "r"(a[2]), "r"(a[3]), "r"(b0), "r"(b1));
}

// Lane selectors for ldmatrix.x4 address generation
__device__ __forceinline__ int lrow_a(int lane) { return lane & 15; }
__device__ __forceinline__ int lcol_a(int lane) { return (lane >> 4) * 8; }
__device__ __forceinline__ int lrow_b(int lane) { return (lane & 7) + ((lane >> 4) << 3); }
__device__ __forceinline__ int lcol_b(int lane) { return ((lane >> 3) & 1) * 8; }

// ---------------------------------------------------------------------------
// fp32 -> fp16 conversions (merged launches)
// ---------------------------------------------------------------------------
__global__ void cvt_f2h_3(const float* __restrict__ i0, const float* __restrict__ i1,
                          const float* __restrict__ i2,
                          __half* __restrict__ o0, __half* __restrict__ o1,
                          __half* __restrict__ o2, int n4)
{
    const int z = blockIdx.z;
    const float* in = (z == 0) ? i0 : (z == 1) ? i1 : i2;
    __half* out     = (z == 0) ? o0 : (z == 1) ? o1 : o2;
    int i = blockIdx.x * blockDim.x + threadIdx.x;
    if (i < n4) {
        float4 v = ((const float4*)in)[i];
        ((__half2*)out)[2 * i]     = __floats2half2_rn(v.x, v.y);
        ((__half2*)out)[2 * i + 1] = __floats2half2_rn(v.z, v.w);
    }
}

// W [K][N] fp32 -> Wt [N][K] fp16 (tiled transpose), 4 weights in one launch
__global__ void cvt_trans_f2h_4(
    const float* __restrict__ w0, const float* __restrict__ w1,
    const float* __restrict__ w2, const float* __restrict__ w3,
    __half* __restrict__ t0, __half* __restrict__ t1,
    __half* __restrict__ t2, __half* __restrict__ t3)
{
    const int z = blockIdx.z;
    const float* W = (z == 0) ? w0 : (z == 1) ? w1 : (z == 2) ? w2 : w3;
    __half* Wt     = (z == 0) ? t0 : (z == 1) ? t1 : (z == 2) ? t2 : t3;

    __shared__ float t[32][33];
    const int n0 = blockIdx.x * 32, k0 = blockIdx.y * 32;
    const int tx = threadIdx.x, ty = threadIdx.y;
    #pragma unroll
    for (int j = 0; j < 32; j += 8)
        t[ty + j][tx] = W[(size_t)(k0 + ty + j) * EE + n0 + tx];
    __syncthreads();
    #pragma unroll
    for (int j = 0; j < 32; j += 8)
        Wt[(size_t)(n0 + ty + j) * EE + k0 + tx] = __float2half_rn(t[tx][ty + j]);
}

// ---------------------------------------------------------------------------
// fp16 tensor-core GEMM (unchanged from passing R13 kernel)
// ---------------------------------------------------------------------------
#define BKH 64
#define XSTRH 72
#define GEMMH3_SMEM (3 * 2 * 128 * XSTRH * 2)   // 110592 B (3 stages, A+B)

template<int IS_QKV>
__global__ __launch_bounds__(256, 2)
void gemm_h3(const __half* __restrict__ X0, const __half* __restrict__ X1,
             const __half* __restrict__ X2,
             const __half* __restrict__ W0, const __half* __restrict__ W1,
             const __half* __restrict__ W2,
             const float* __restrict__ B0, const float* __restrict__ B1,
             const float* __restrict__ B2,
             void* __restrict__ Y0, void* __restrict__ Y1, void* __restrict__ Y2)
{
    const __half* X;
    const __half* Wt;
    const float* bias;
    void* Yv;
    int mode;
    if (IS_QKV) {
        const int z = blockIdx.z;
        X    = (z == 0) ? X0 : (z == 1) ? X1 : X2;
        Wt   = (z == 0) ? W0 : (z == 1) ? W1 : W2;
        bias = (z == 0) ? B0 : (z == 1) ? B1 : B2;
        Yv   = (z == 0) ? Y0 : (z == 1) ? Y1 : Y2;
        mode = (z == 2) ? 2 : 1;
    } else {
        X = X0; Wt = W0; bias = B0; Yv = Y0; mode = 0;
    }

    extern __shared__ __half smg[];
    const int tid  = threadIdx.x;
    const int lane = tid & 31;
    const int warp = tid >> 5;
    const int g = lane >> 2, t = lane & 3;
    const int wm = (warp >> 2) * 64;
    const int wn = (warp & 3) * 32;
    const int m0 = blockIdx.y * 128, n0 = blockIdx.x * 128;

    const int ra = lrow_a(lane), ca = lcol_a(lane);
    const int rb = lrow_b(lane), cb = lcol_b(lane);

    float acc[4][4][4];
    #pragma unroll
    for (int mi = 0; mi < 4; mi++)
        #pragma unroll
        for (int ni = 0; ni < 4; ni++)
            #pragma unroll
            for (int r = 0; r < 4; r++) acc[mi][ni][r] = 0.f;

    auto issue = [&](int stage, int k0) {
        __half* xs = smg + stage * 2 * 128 * XSTRH;
        __half* ws = xs + 128 * XSTRH;
        #pragma unroll
        for (int j = 0; j < 4; j++) {
            int c = tid + j * 256;          // 0..1023
            int r = c >> 3, ch = c & 7;     // 128 rows x 8 chunks (64 halves)
            uint32_t sa = (uint32_t)__cvta_generic_to_shared(xs + r * XSTRH + ch * 8);
            CP_ASYNC16(sa, X + (size_t)(m0 + r) * EE + k0 + ch * 8);
            uint32_t sb = (uint32_t)__cvta_generic_to_shared(ws + r * XSTRH + ch * 8);
            CP_ASYNC16(sb, Wt + (size_t)(n0 + r) * EE + k0 + ch * 8);
        }
    };

    const int NT = EE / BKH;  // 32
    issue(0, 0);       CP_COMMIT();
    issue(1, BKH);     CP_COMMIT();

    for (int it = 0; it < NT; it++) {
        const int s = it % 3;
        if (it + 1 < NT) CP_WAIT1();
        else             CP_WAIT0();
        __syncthreads();

        const __half* xs = smg + s * 2 * 128 * XSTRH;
        const __half* ws = xs + 128 * XSTRH;

        #pragma unroll
        for (int ks = 0; ks < 4; ks++) {
            uint32_t a[4][4], b[4][2];
            #pragma unroll
            for (int mi = 0; mi < 4; mi++) {
                uint32_t ad = (uint32_t)__cvta_generic_to_shared(
                    xs + (wm + mi * 16 + ra) * XSTRH + 16 * ks + ca);
                LDSM_X4(a[mi][0], a[mi][1], a[mi][2], a[mi][3], ad);
            }
            #pragma unroll
            for (int ni2 = 0; ni2 < 2; ni2++) {
                uint32_t bd = (uint32_t)__cvta_generic_to_shared(
                    ws + (wn + ni2 * 16 + rb) * XSTRH + 16 * ks + cb);
                LDSM_X4(b[2 * ni2][0], b[2 * ni2][1],
                        b[2 * ni2 + 1][0], b[2 * ni2 + 1][1], bd);
            }
            #pragma unroll
            for (int mi = 0; mi < 4; mi++)
                #pragma unroll
                for (int ni = 0; ni < 4; ni++)
                    mma_f16(acc[mi][ni], a[mi], b[ni][0], b[ni][1]);
        }
        __syncthreads();

        if (it + 2 < NT) {
            issue((it + 2) % 3, (it + 2) * BKH);
            CP_COMMIT();
        }
    }

    // Epilogue
    #pragma unroll
    for (int mi = 0; mi < 4; mi++) {
        #pragma unroll
        for (int ni = 0; ni < 4; ni++) {
            int row = m0 + wm + mi * 16 + g;
            int cl  = wn + ni * 8 + 2 * t;
            int n   = n0 + cl;
            float bx = bias[n], by = bias[n + 1];
            float c00 = acc[mi][ni][0] + bx, c01 = acc[mi][ni][1] + by;
            float c10 = acc[mi][ni][2] + bx, c11 = acc[mi][ni][3] + by;
            if (mode == 0) {
                float* Y = (float*)Yv;
                *(float2*)(Y + (size_t)row * EE + n)       = make_float2(c00, c01);
                *(float2*)(Y + (size_t)(row + 8) * EE + n) = make_float2(c10, c11);
            } else if (mode == 1) {
                __half* Y = (__half*)Yv;
                int b0r = row >> 11, s = row & (SS - 1);
                int s2 = (row + 8) & (SS - 1);
                __half* base = Y + ((size_t)(b0r * HH + blockIdx.x) * SS + s) * DD + cl;
                *(__half2*)base = __floats2half2_rn(c00, c01);
                __half* base2 = Y + ((size_t)(b0r * HH + blockIdx.x) * SS + s2) * DD + cl;
                *(__half2*)base2 = __floats2half2_rn(c10, c11);
            } else {
                __half* Y = (__half*)Yv;
                int b0r = row >> 11, s = row & (SS - 1);
                int s2 = (row + 8) & (SS - 1);
                __half* colp = Y + ((size_t)(b0r * HH + blockIdx.x) * DD + cl) * SS;
                colp[s]  = __float2half_rn(c00);
                colp[s2] = __float2half_rn(c10);
                __half* colp2 = colp + SS;
                colp2[s]  = __float2half_rn(c01);
                colp2[s2] = __float2half_rn(c11);
            }
        }
    }
}

// ---------------------------------------------------------------------------
// fp16 tensor-core flash attention — 128 threads / Q-tile 64 (occupancy 2 CTA/SM)
// Per-warp work identical to previous version (16 q-rows x 128 d); only the
// CTA shape and loader index maps changed.
// ---------------------------------------------------------------------------
#define ATHR 128
#define AWARPS 4
#define TKH 64
#define KSTRH 136
#define VSTRH 72
#define PSTRH 72
#define ATTNH_SMEM ((2*TKH*KSTRH + 2*DD*VSTRH + AWARPS*16*PSTRH) * 2)

__global__ __launch_bounds__(ATHR, 2)
void attn_h(const __half* __restrict__ Q, const __half* __restrict__ K,
            const __half* __restrict__ Vt, __half* __restrict__ AO)
{
    extern __shared__ __half smh[];
    __half* Kb = smh;                       // [2][TKH][KSTRH]
    __half* Vb = smh + 2 * TKH * KSTRH;     // [2][DD][VSTRH]
    __half* Pw = Vb + 2 * DD * VSTRH;       // [AWARPS][16][PSTRH]

    const int tid  = threadIdx.x;
    const int lane = tid & 31;
    const int warp = tid >> 5;              // 0..3
    const int g = lane >> 2, t = lane & 3;
    const int bh = blockIdx.y;
    const int q0 = blockIdx.x * 64;

    const int ra = lrow_a(lane), ca = lcol_a(lane);
    const int rb = lrow_b(lane), cb = lcol_b(lane);

    const __half* Qg = Q + ((size_t)bh * SS + q0) * DD;
    const __half* Kg = K + (size_t)bh * SS * DD;
    const __half* Vg = Vt + (size_t)bh * DD * SS;   // [d][s]

    // ---- stage Q (64 rows x 128 halves = 1024 chunks) into Kb, then regs ----
    #pragma unroll
    for (int j = 0; j < 8; j++) {
        int c = tid + j * ATHR;             // 0..1023
        int r = c >> 4, ch = c & 15;
        uint32_t sa = (uint32_t)__cvta_generic_to_shared(Kb + r * KSTRH + ch * 8);
        CP_ASYNC16(sa, Qg + (size_t)r * DD + ch * 8);
    }
    CP_COMMIT(); CP_WAIT0();
    __syncthreads();

    uint32_t qa[8][4];
    #pragma unroll
    for (int ks = 0; ks < 8; ks++) {
        uint32_t ad = (uint32_t)__cvta_generic_to_shared(
            Kb + (warp * 16 + ra) * KSTRH + 16 * ks + ca);
        LDSM_X4(qa[ks][0], qa[ks][1], qa[ks][2], qa[ks][3], ad);
    }
    __syncthreads();

    float oacc[16][4];
    #pragma unroll
    for (int n = 0; n < 16; n++)
        #pragma unroll
        for (int r = 0; r < 4; r++) oacc[n][r] = 0.f;
    float m_a = -1e30f, m_b = -1e30f, l_a = 0.f, l_b = 0.f;

    const float scale = 0.08838834764831845f;  // 1/sqrt(128)

    auto load_kv = [&](int stage, int kt) {
        __half* ks_ = Kb + stage * TKH * KSTRH;
        __half* vs_ = Vb + stage * DD * VSTRH;
        #pragma unroll
        for (int j = 0; j < 8; j++) {       // K: 64 rows x 16 chunks = 1024
            int c = tid + j * ATHR;
            int r = c >> 4, ch = c & 15;
            uint32_t sk = (uint32_t)__cvta_generic_to_shared(ks_ + r * KSTRH + ch * 8);
            CP_ASYNC16(sk, Kg + (size_t)(kt + r) * DD + ch * 8);
        }
        #pragma unroll
        for (int j = 0; j < 8; j++) {       // Vt: 128 d-rows x 8 chunks = 1024
            int c = tid + j * ATHR;
            int r = c >> 3, ch = c & 7;
            uint32_t sv = (uint32_t)__cvta_generic_to_shared(vs_ + r * VSTRH + ch * 8);
            CP_ASYNC16(sv, Vg + (size_t)r * SS + kt + ch * 8);
        }
    };

    load_kv(0, 0);
    CP_COMMIT();

    const int NTILES = SS / TKH;  // 32
    for (int it = 0; it < NTILES; it++) {
        if (it + 1 < NTILES) {
            load_kv((it + 1) & 1, (it + 1) * TKH);
            CP_COMMIT();
            CP_WAIT1();
        } else {
            CP_WAIT0();
        }
        __syncthreads();

        const __half* ks_ = Kb + (it & 1) * TKH * KSTRH;
        const __half* vs_ = Vb + (it & 1) * DD * VSTRH;

        // ---- S = Q K^T ----
        float sacc[8][4];
        #pragma unroll
        for (int n = 0; n < 8; n++)
            #pragma unroll
            for (int r = 0; r < 4; r++) sacc[n][r] = 0.f;

        #pragma unroll
        for (int ks = 0; ks < 8; ks++) {
            uint32_t b[8][2];
            #pragma unroll
            for (int ni2 = 0; ni2 < 4; ni2++) {
                uint32_t bd = (uint32_t)__cvta_generic_to_shared(
                    ks_ + (ni2 * 16 + rb) * KSTRH + 16 * ks + cb);
                LDSM_X4(b[2 * ni2][0], b[2 * ni2][1],
                        b[2 * ni2 + 1][0], b[2 * ni2 + 1][1], bd);
            }
            #pragma unroll
            for (int nt = 0; nt < 8; nt++)
                mma_f16(sacc[nt], qa[ks], b[nt][0], b[nt][1]);
        }

        // ---- online softmax (rows g, g+8; 4 lanes/row via xor 1,2) ----
        float mxa = -1e30f, mxb = -1e30f;
        #pragma unroll
        for (int nt = 0; nt < 8; nt++) {
            sacc[nt][0] *= scale; sacc[nt][1] *= scale;
            sacc[nt][2] *= scale; sacc[nt][3] *= scale;
            mxa = fmaxf(mxa, fmaxf(sacc[nt][0], sacc[nt][1]));
            mxb = fmaxf(mxb, fmaxf(sacc[nt][2], sacc[nt][3]));
        }
        mxa = fmaxf(mxa, __shfl_xor_sync(0xffffffffu, mxa, 1));
        mxa = fmaxf(mxa, __shfl_xor_sync(0xffffffffu, mxa, 2));
        mxb = fmaxf(mxb, __shfl_xor_sync(0xffffffffu, mxb, 1));
        mxb = fmaxf(mxb, __shfl_xor_sync(0xffffffffu, mxb, 2));

        float mna = fmaxf(m_a, mxa), mnb = fmaxf(m_b, mxb);
        float ca2 = __expf(m_a - mna), cb2 = __expf(m_b - mnb);
        m_a = mna; m_b = mnb;

        float ra2 = 0.f, rb2 = 0.f;
        __half* pw = Pw + warp * 16 * PSTRH;
        #pragma unroll
        for (int nt = 0; nt < 8; nt++) {
            __half h0 = __float2half_rn(__expf(sacc[nt][0] - mna));
            __half h1 = __float2half_rn(__expf(sacc[nt][1] - mna));
            __half h2 = __float2half_rn(__expf(sacc[nt][2] - mnb));
            __half h3 = __float2half_rn(__expf(sacc[nt][3] - mnb));
            ra2 += __half2float(h0) + __half2float(h1);
            rb2 += __half2float(h2) + __half2float(h3);
            __half2 pa01; pa01.x = h0; pa01.y = h1;
            __half2 pa23; pa23.x = h2; pa23.y = h3;
            *(__half2*)&pw[g * PSTRH + nt * 8 + 2 * t]       = pa01;
            *(__half2*)&pw[(g + 8) * PSTRH + nt * 8 + 2 * t] = pa23;
        }
        ra2 += __shfl_xor_sync(0xffffffffu, ra2, 1);
        ra2 += __shfl_xor_sync(0xffffffffu, ra2, 2);
        rb2 += __shfl_xor_sync(0xffffffffu, rb2, 1);
        rb2 += __shfl_xor_sync(0xffffffffu, rb2, 2);
        l_a = l_a * ca2 + ra2;
        l_b = l_b * cb2 + rb2;

        #pragma unroll
        for (int n = 0; n < 16; n++) {
            oacc[n][0] *= ca2; oacc[n][1] *= ca2;
            oacc[n][2] *= cb2; oacc[n][3] *= cb2;
        }
        __syncwarp();  // P visible within warp

        // ---- O += P V ----
        #pragma unroll
        for (int k2 = 0; k2 < 4; k2++) {
            uint32_t pa[4];
            uint32_t pd = (uint32_t)__cvta_generic_to_shared(
                pw + ra * PSTRH + 16 * k2 + ca);
            LDSM_X4(pa[0], pa[1], pa[2], pa[3], pd);
            #pragma unroll
            for (int ni2 = 0; ni2 < 8; ni2++) {
                uint32_t b[4];
                uint32_t bd = (uint32_t)__cvta_generic_to_shared(
                    vs_ + (ni2 * 16 + rb) * VSTRH + 16 * k2 + cb);
                LDSM_X4(b[0], b[1], b[2], b[3], bd);
                mma_f16(oacc[2 * ni2],     pa, b[0], b[1]);
                mma_f16(oacc[2 * ni2 + 1], pa, b[2], b[3]);
            }
        }
        __syncthreads();
    }

    // ---- epilogue: normalize + store AO fp16 (B,S,E) ----
    const float ia = 1.0f / l_a, ib = 1.0f / l_b;
    const int b = bh / HH, h = bh % HH;
    const int rowa = q0 + warp * 16 + g, rowb = rowa + 8;
    __half* opa = AO + ((size_t)(b * SS + rowa)) * EE + h * DD;
    __half* opb = AO + ((size_t)(b * SS + rowb)) * EE + h * DD;
    #pragma unroll
    for (int nt2 = 0; nt2 < 16; nt2++) {
        int cl = nt2 * 8 + 2 * t;
        *(__half2*)(opa + cl) = __floats2half2_rn(oacc[nt2][0] * ia, oacc[nt2][1] * ia);
        *(__half2*)(opb + cl) = __floats2half2_rn(oacc[nt2][2] * ib, oacc[nt2][3] * ib);
    }
}

// ---------------------------------------------------------------------------
extern "C" void kernel_launch(void* const* d_in, const int* in_sizes, int n_in,
                              void* d_out, int out_size)
{
    const float* query  = (const float*)d_in[0];
    const float* key_in = (const float*)d_in[1];
    const float* value  = (const float*)d_in[2];
    const float* Wq = (const float*)d_in[3];
    const float* bq = (const float*)d_in[4];
    const float* Wk = (const float*)d_in[5];
    const float* bk = (const float*)d_in[6];
    const float* Wv = (const float*)d_in[7];
    const float* bv = (const float*)d_in[8];
    const float* Wo = (const float*)d_in[9];
    const float* bo = (const float*)d_in[10];
    float* out = (float*)d_out;

    __half *hq, *hk, *hv, *hWq, *hWk, *hWv, *hWo;
    __half *qbuf, *kbuf, *vtbuf, *aobuf;
    cudaGetSymbolAddress((void**)&hq,  g_hq);
    cudaGetSymbolAddress((void**)&hk,  g_hk);
    cudaGetSymbolAddress((void**)&hv,  g_hv);
    cudaGetSymbolAddress((void**)&hWq, g_hWq);
    cudaGetSymbolAddress((void**)&hWk, g_hWk);
    cudaGetSymbolAddress((void**)&hWv, g_hWv);
    cudaGetSymbolAddress((void**)&hWo, g_hWo);
    cudaGetSymbolAddress((void**)&qbuf,  g_Q);
    cudaGetSymbolAddress((void**)&kbuf,  g_K);
    cudaGetSymbolAddress((void**)&vtbuf, g_Vt);
    cudaGetSymbolAddress((void**)&aobuf, g_AO);

    cudaFuncSetAttribute(attn_h,
                         cudaFuncAttributeMaxDynamicSharedMemorySize, ATTNH_SMEM);
    cudaFuncSetAttribute(gemm_h3<0>,
                         cudaFuncAttributeMaxDynamicSharedMemorySize, GEMMH3_SMEM);
    cudaFuncSetAttribute(gemm_h3<1>,
                         cudaFuncAttributeMaxDynamicSharedMemorySize, GEMMH3_SMEM);

    // 1. fp16 conversions (2 launches)
    const int NX4 = MM * EE / 4;
    dim3 cgrid((NX4 + 255) / 256, 1, 3);
    cvt_f2h_3<<<cgrid, 256>>>(query, key_in, value, hq, hk, hv, NX4);
    dim3 tgrid(EE / 32, EE / 32, 4), tblock(32, 8);
    cvt_trans_f2h_4<<<tgrid, tblock>>>(Wq, Wk, Wv, Wo, hWq, hWk, hWv, hWo);

    // 2. Q/K/V projections in ONE launch (z selects GEMM)
    dim3 qkvgrid(EE / 128, MM / 128, 3);   // (16, 32, 3)
    gemm_h3<1><<<qkvgrid, 256, GEMMH3_SMEM>>>(
        hq, hk, hv, hWq, hWk, hWv, bq, bk, bv, qbuf, kbuf, vtbuf);

    // 3. Fused fp16 tensor-core attention -> (B,S,E) fp16 (Q tile 64, 2 CTA/SM)
    dim3 agrid(SS / 64, BB * HH);    // (32, 32)
    attn_h<<<agrid, ATHR, ATTNH_SMEM>>>(qbuf, kbuf, vtbuf, aobuf);

    // 4. Output projection -> d_out fp32
    dim3 ogrid(EE / 128, MM / 128, 1);
    gemm_h3<0><<<ogrid, 256, GEMMH3_SMEM>>>(
        aobuf, nullptr, nullptr, hWo, nullptr, nullptr,
        bo, nullptr, nullptr, out, nullptr, nullptr);
}